// round 2
// baseline (speedup 1.0000x reference)
#include <cuda_runtime.h>
#include <math.h>

// Problem constants
#define BB 4
#define SS 2048
#define DD 1024
#define MS (BB*SS)          // 8192 rows

// GEMM tiling
#define BM 128
#define BN 128
#define BK 16
#define TM 8
#define TN 8
#define NTHREADS 256

// Scratch (no allocations allowed -> device globals)
__device__ float g_cproj[MS*DD];          // 32 MB
__device__ float g_qproj[MS*DD];          // 32 MB
__device__ float g_iface[MS*DD];          // 32 MB
__device__ float g_sim[(size_t)BB*SS*SS]; // 64 MB

// ---------------------------------------------------------------------------
// NT GEMM: C[m,n] = sum_k A[m,k] * B[n,k]  (both row-major, contract fast dim)
// lda = physical row stride of A (and A2). For the concat case the logical K
// (2048) differs from the physical stride (1024): k >= Ksplit reads A2.
// mode 0: C = acc + bias[n]      (bias may be null)
// mode 1: C = sigmoid(acc + bias[n])
// Batched via blockIdx.z with element strides.
// ---------------------------------------------------------------------------
__global__ __launch_bounds__(NTHREADS)
void gemm_nt_kernel(const float* __restrict__ A,
                    const float* __restrict__ A2,
                    const float* __restrict__ B,
                    const float* __restrict__ bias,
                    float* __restrict__ C,
                    int M, int N, int K, int Ksplit, int lda,
                    long As_batch, long Bs_batch, long Cs_batch,
                    int mode)
{
    __shared__ float As[BK][BM];
    __shared__ float Bs[BK][BN];

    int bz = blockIdx.z;
    A += bz * As_batch;
    if (A2) A2 += bz * As_batch;
    B += bz * Bs_batch;
    C += bz * Cs_batch;

    int row0 = blockIdx.y * BM;
    int col0 = blockIdx.x * BN;
    int tid  = threadIdx.x;
    int tx   = tid & 15;
    int ty   = tid >> 4;

    // tile-load mapping: 4 threads per 16-wide row, float4 each
    int lrow = tid >> 2;          // 0..63
    int lcol = (tid & 3) * 4;     // 0,4,8,12

    float acc[TM][TN];
    #pragma unroll
    for (int i = 0; i < TM; i++)
        #pragma unroll
        for (int j = 0; j < TN; j++) acc[i][j] = 0.0f;

    for (int kt = 0; kt < K; kt += BK) {
        const float* Ap;
        int kA;
        if (kt < Ksplit) { Ap = A;  kA = kt; }
        else             { Ap = A2; kA = kt - Ksplit; }

        #pragma unroll
        for (int r = 0; r < 2; r++) {
            int rr = lrow + r * 64;
            float4 v = *reinterpret_cast<const float4*>(
                &Ap[(long)(row0 + rr) * lda + kA + lcol]);
            As[lcol + 0][rr] = v.x;
            As[lcol + 1][rr] = v.y;
            As[lcol + 2][rr] = v.z;
            As[lcol + 3][rr] = v.w;
        }
        #pragma unroll
        for (int r = 0; r < 2; r++) {
            int rr = lrow + r * 64;
            float4 v = *reinterpret_cast<const float4*>(
                &B[(long)(col0 + rr) * K + kt + lcol]);
            Bs[lcol + 0][rr] = v.x;
            Bs[lcol + 1][rr] = v.y;
            Bs[lcol + 2][rr] = v.z;
            Bs[lcol + 3][rr] = v.w;
        }
        __syncthreads();

        #pragma unroll
        for (int kk = 0; kk < BK; kk++) {
            float a[TM], b[TN];
            #pragma unroll
            for (int i = 0; i < TM; i++) a[i] = As[kk][ty * TM + i];
            #pragma unroll
            for (int j = 0; j < TN; j++) b[j] = Bs[kk][tx * TN + j];
            #pragma unroll
            for (int i = 0; i < TM; i++)
                #pragma unroll
                for (int j = 0; j < TN; j++)
                    acc[i][j] += a[i] * b[j];
        }
        __syncthreads();
    }

    #pragma unroll
    for (int i = 0; i < TM; i++) {
        int r = row0 + ty * TM + i;
        #pragma unroll
        for (int j = 0; j < TN; j++) {
            int c = col0 + tx * TN + j;
            float v = acc[i][j];
            if (bias) v += bias[c];
            if (mode == 1) v = 1.0f / (1.0f + expf(-v));
            C[(long)r * N + c] = v;
        }
    }
}

// ---------------------------------------------------------------------------
// NN GEMM with fused final epilogue:
//   out[m,n] = Cls[m,n] + Ifc[m,n] * ( sum_k A[m,k] * B[k,n] )
// A: [M,K] row-major (attention), B: [K,N] row-major (quantum)
// ---------------------------------------------------------------------------
__global__ __launch_bounds__(NTHREADS)
void gemm_nn_epi_kernel(const float* __restrict__ A,
                        const float* __restrict__ B,
                        const float* __restrict__ Cls,
                        const float* __restrict__ Ifc,
                        float* __restrict__ C,
                        int M, int N, int K,
                        long As_batch, long Bs_batch, long Cs_batch)
{
    __shared__ float As[BK][BM];
    __shared__ float Bs[BK][BN];

    int bz = blockIdx.z;
    A   += bz * As_batch;
    B   += bz * Bs_batch;
    Cls += bz * Cs_batch;
    Ifc += bz * Cs_batch;
    C   += bz * Cs_batch;

    int row0 = blockIdx.y * BM;
    int col0 = blockIdx.x * BN;
    int tid  = threadIdx.x;
    int tx   = tid & 15;
    int ty   = tid >> 4;

    // A-tile load (same as NT): 4 threads per row of 16
    int arow = tid >> 2;
    int acol = (tid & 3) * 4;
    // B-tile load: 32 threads per row of 128, float4 each
    int brow = tid >> 5;          // 0..7
    int bcol = (tid & 31) * 4;    // 0..124

    float acc[TM][TN];
    #pragma unroll
    for (int i = 0; i < TM; i++)
        #pragma unroll
        for (int j = 0; j < TN; j++) acc[i][j] = 0.0f;

    for (int kt = 0; kt < K; kt += BK) {
        #pragma unroll
        for (int r = 0; r < 2; r++) {
            int rr = arow + r * 64;
            float4 v = *reinterpret_cast<const float4*>(
                &A[(long)(row0 + rr) * K + kt + acol]);
            As[acol + 0][rr] = v.x;
            As[acol + 1][rr] = v.y;
            As[acol + 2][rr] = v.z;
            As[acol + 3][rr] = v.w;
        }
        #pragma unroll
        for (int r = 0; r < 2; r++) {
            int rr = brow + r * 8;
            float4 v = *reinterpret_cast<const float4*>(
                &B[(long)(kt + rr) * N + col0 + bcol]);
            *reinterpret_cast<float4*>(&Bs[rr][bcol]) = v;
        }
        __syncthreads();

        #pragma unroll
        for (int kk = 0; kk < BK; kk++) {
            float a[TM], b[TN];
            #pragma unroll
            for (int i = 0; i < TM; i++) a[i] = As[kk][ty * TM + i];
            #pragma unroll
            for (int j = 0; j < TN; j++) b[j] = Bs[kk][tx * TN + j];
            #pragma unroll
            for (int i = 0; i < TM; i++)
                #pragma unroll
                for (int j = 0; j < TN; j++)
                    acc[i][j] += a[i] * b[j];
        }
        __syncthreads();
    }

    #pragma unroll
    for (int i = 0; i < TM; i++) {
        int r = row0 + ty * TM + i;
        #pragma unroll
        for (int j = 0; j < TN; j++) {
            int c = col0 + tx * TN + j;
            long idx = (long)r * N + c;
            C[idx] = Cls[idx] + Ifc[idx] * acc[i][j];
        }
    }
}

// ---------------------------------------------------------------------------
// Row softmax over S=2048 elements, scaled by (1/sqrt(D))/temperature.
// One block (256 threads) per row; 8 elements per thread; in-place.
// ---------------------------------------------------------------------------
__global__ __launch_bounds__(256)
void softmax_kernel(float* __restrict__ sim, const float* __restrict__ temp)
{
    __shared__ float red_max[8];
    __shared__ float red_sum[8];

    long row = blockIdx.x;
    float* p = sim + row * (long)SS;
    int tid  = threadIdx.x;
    int lane = tid & 31;
    int wid  = tid >> 5;

    float s = (1.0f / 32.0f) / (*temp);   // 1/sqrt(1024) / T

    float v[8];
    float mx = -INFINITY;
    #pragma unroll
    for (int i = 0; i < 8; i++) {
        v[i] = p[tid + i * 256] * s;
        mx = fmaxf(mx, v[i]);
    }
    #pragma unroll
    for (int o = 16; o > 0; o >>= 1)
        mx = fmaxf(mx, __shfl_xor_sync(0xffffffffu, mx, o));
    if (lane == 0) red_max[wid] = mx;
    __syncthreads();
    mx = red_max[0];
    #pragma unroll
    for (int w = 1; w < 8; w++) mx = fmaxf(mx, red_max[w]);

    float sum = 0.0f;
    #pragma unroll
    for (int i = 0; i < 8; i++) {
        v[i] = expf(v[i] - mx);
        sum += v[i];
    }
    #pragma unroll
    for (int o = 16; o > 0; o >>= 1)
        sum += __shfl_xor_sync(0xffffffffu, sum, o);
    if (lane == 0) red_sum[wid] = sum;
    __syncthreads();
    sum = 0.0f;
    #pragma unroll
    for (int w = 0; w < 8; w++) sum += red_sum[w];

    float inv = 1.0f / sum;
    #pragma unroll
    for (int i = 0; i < 8; i++)
        p[tid + i * 256] = v[i] * inv;
}

// ---------------------------------------------------------------------------
extern "C" void kernel_launch(void* const* d_in, const int* in_sizes, int n_in,
                              void* d_out, int out_size)
{
    const float* classical = (const float*)d_in[0];
    const float* quantum   = (const float*)d_in[1];
    const float* Wc        = (const float*)d_in[2];
    const float* bc        = (const float*)d_in[3];
    const float* Wq        = (const float*)d_in[4];
    const float* bq        = (const float*)d_in[5];
    const float* Wg        = (const float*)d_in[6];
    const float* bg        = (const float*)d_in[7];
    const float* temp      = (const float*)d_in[8];
    float* out             = (float*)d_out;

    float *cproj, *qproj, *iface, *sim;
    cudaGetSymbolAddress((void**)&cproj, g_cproj);
    cudaGetSymbolAddress((void**)&qproj, g_qproj);
    cudaGetSymbolAddress((void**)&iface, g_iface);
    cudaGetSymbolAddress((void**)&sim,   g_sim);

    dim3 blk(NTHREADS);

    // 1) c_proj = classical @ Wc^T + bc    [8192,1024]
    gemm_nt_kernel<<<dim3(DD/BN, MS/BM, 1), blk>>>(
        classical, nullptr, Wc, bc, cproj,
        MS, DD, DD, DD, DD, 0, 0, 0, 0);

    // 2) q_proj = quantum @ Wq^T + bq
    gemm_nt_kernel<<<dim3(DD/BN, MS/BM, 1), blk>>>(
        quantum, nullptr, Wq, bq, qproj,
        MS, DD, DD, DD, DD, 0, 0, 0, 0);

    // 3) interface = sigmoid([c_proj|q_proj] @ Wg^T + bg)
    //    logical K=2048 split at 1024; physical row stride of cproj/qproj = 1024
    gemm_nt_kernel<<<dim3(DD/BN, MS/BM, 1), blk>>>(
        cproj, qproj, Wg, bg, iface,
        MS, DD, 2*DD, DD, DD, 0, 0, 0, 1);

    // 4) sim[b] = c_proj[b] @ q_proj[b]^T  (raw dot, scale folded into softmax)
    gemm_nt_kernel<<<dim3(SS/BN, SS/BM, BB), blk>>>(
        cproj, nullptr, qproj, nullptr, sim,
        SS, SS, DD, DD, DD,
        (long)SS*DD, (long)SS*DD, (long)SS*SS, 0);

    // 5) row softmax with (1/sqrt(D))/T scaling, in place
    softmax_kernel<<<BB*SS, 256>>>(sim, temp);

    // 6) out = classical + interface * (attn[b] @ quantum[b])
    gemm_nn_epi_kernel<<<dim3(DD/BN, SS/BM, BB), blk>>>(
        sim, quantum, classical, iface, out,
        SS, DD, SS,
        (long)SS*SS, (long)SS*DD, (long)SS*DD);
}

// round 4
// speedup vs baseline: 4.1561x; 4.1561x over previous
#include <cuda_runtime.h>
#include <math.h>
#include <stdint.h>

// Problem constants
#define BB 4
#define SS 2048
#define DD 1024
#define MS (BB*SS)          // 8192 rows

#define KC  32              // K floats per chunk (128B rows in smem)
#define SM_BUF 16384        // one 128x32 fp32 tile
#define SM_TOTAL (4*SM_BUF) // A0,B0,A1,B1

// Scratch (no allocations allowed -> device globals)
__device__ float g_cproj[MS*DD];           // 32 MB
__device__ float g_qproj[MS*DD];           // 32 MB
__device__ float g_iface[MS*DD];           // 32 MB
__device__ float g_qT[(size_t)BB*DD*SS];   // 32 MB  (quantum transposed per batch)
__device__ float g_sim[(size_t)BB*SS*SS];  // 64 MB

// ---------------------------------------------------------------------------
__device__ __forceinline__ uint32_t smem_u32(const void* p) {
    uint32_t a;
    asm("{ .reg .u64 t; cvta.to.shared.u64 t, %1; cvt.u32.u64 %0, t; }" : "=r"(a) : "l"(p));
    return a;
}

#define CP_COMMIT() asm volatile("cp.async.commit_group;" ::: "memory")
#define CP_WAIT(n)  asm volatile("cp.async.wait_group %0;" :: "n"(n) : "memory")

// Load one 128-row x 32-float chunk, global->smem via cp.async with XOR swizzle.
// 128 threads, 8 float4 each. Swizzle: float4 seg s of row r stored at s ^ (r&7).
__device__ __forceinline__ void load_chunk(const float* __restrict__ src, int ld,
                                           int row0, int kc, uint32_t sbuf, int tid) {
    #pragma unroll
    for (int i = 0; i < 8; i++) {
        int idx = i * 128 + tid;
        int row = idx >> 3;
        int seg = idx & 7;
        const float* gp = src + (long)(row0 + row) * ld + kc + seg * 4;
        uint32_t off = sbuf + row * 128 + ((seg ^ (row & 7)) << 4);
        asm volatile("cp.async.cg.shared.global [%0], [%1], 16;" :: "r"(off), "l"(gp));
    }
}

// Fragment element: load fp32 from swizzled smem, round to tf32 (rna)
__device__ __forceinline__ uint32_t ldcvt(uint32_t base, int row, int col) {
    uint32_t addr = base + row * 128 + ((((col >> 2) ^ (row & 7)) << 4) | ((col & 3) << 2));
    float v;
    asm volatile("ld.shared.f32 %0, [%1];" : "=f"(v) : "r"(addr));
    uint32_t t;
    asm volatile("cvt.rna.tf32.f32 %0, %1;" : "=r"(t) : "f"(v));
    return t;
}

__device__ __forceinline__ void mma8(float* c, const uint32_t* a, const uint32_t* b) {
    asm volatile("mma.sync.aligned.m16n8k8.row.col.f32.tf32.tf32.f32 "
                 "{%0,%1,%2,%3}, {%4,%5,%6,%7}, {%8,%9}, {%0,%1,%2,%3};"
                 : "+f"(c[0]), "+f"(c[1]), "+f"(c[2]), "+f"(c[3])
                 : "r"(a[0]), "r"(a[1]), "r"(a[2]), "r"(a[3]), "r"(b[0]), "r"(b[1]));
}

// ---------------------------------------------------------------------------
// NT tf32 tensor-core GEMM: C[m,n] = epi( sum_k A[m,k] * B[n,k] )
// A-concat: chunk k >= Ksplit reads A2[m, k-Ksplit] (same lda).
// mode 0: +bias   1: sigmoid(+bias)   2: raw   3: Cls + Ifc * acc
// ---------------------------------------------------------------------------
__global__ __launch_bounds__(128, 2)
void gemm_tc_kernel(const float* __restrict__ A,
                    const float* __restrict__ A2,
                    const float* __restrict__ B,
                    const float* __restrict__ bias,
                    const float* __restrict__ Cls,
                    const float* __restrict__ Ifc,
                    float* __restrict__ C,
                    int N, int K, int Ksplit, int lda,
                    long As_batch, long Bs_batch, long Cs_batch,
                    int mode)
{
    extern __shared__ char smem[];
    uint32_t sb = smem_u32(smem);

    int tid  = threadIdx.x;
    int wid  = tid >> 5;
    int lane = tid & 31;
    int g    = lane >> 2;      // 0..7
    int tig  = lane & 3;       // 0..3
    int mw   = (wid >> 1) * 64;
    int nw   = (wid & 1) * 64;

    int bz = blockIdx.z;
    A += bz * As_batch;
    if (A2) A2 += bz * As_batch;
    B += bz * Bs_batch;
    if (Cls) Cls += bz * Cs_batch;
    if (Ifc) Ifc += bz * Cs_batch;
    C += bz * Cs_batch;

    int row0 = blockIdx.y * 128;
    int col0 = blockIdx.x * 128;

    float acc[4][8][4];
    #pragma unroll
    for (int i = 0; i < 4; i++)
        #pragma unroll
        for (int j = 0; j < 8; j++)
            #pragma unroll
            for (int q = 0; q < 4; q++) acc[i][j][q] = 0.0f;

    const int NC = K / KC;

    // prologue: chunk 0 -> buffer 0
    {
        const float* Ap = (0 < Ksplit) ? A : A2;
        load_chunk(Ap, lda, row0, 0, sb, tid);
        load_chunk(B,  K,   col0, 0, sb + SM_BUF, tid);
        CP_COMMIT();
    }

    for (int ch = 0; ch < NC; ch++) {
        int cur = ch & 1;
        if (ch + 1 < NC) {
            int kt = (ch + 1) * KC;
            const float* Ap; int kA;
            if (kt < Ksplit) { Ap = A;  kA = kt; }
            else             { Ap = A2; kA = kt - Ksplit; }
            uint32_t nb = sb + ((ch + 1) & 1) * 2 * SM_BUF;
            load_chunk(Ap, lda, row0, kA, nb, tid);
            load_chunk(B,  K,   col0, kt, nb + SM_BUF, tid);
            CP_COMMIT();
            CP_WAIT(1);
        } else {
            CP_WAIT(0);
        }
        __syncthreads();

        uint32_t Ab = sb + cur * 2 * SM_BUF;
        uint32_t Bb = Ab + SM_BUF;

        #pragma unroll
        for (int ks = 0; ks < 4; ks++) {
            int kk = ks * 8;
            uint32_t af[4][4], bf[8][2];
            #pragma unroll
            for (int i = 0; i < 4; i++) {
                int r0 = mw + 16 * i + g;
                af[i][0] = ldcvt(Ab, r0,     kk + tig);
                af[i][1] = ldcvt(Ab, r0 + 8, kk + tig);
                af[i][2] = ldcvt(Ab, r0,     kk + tig + 4);
                af[i][3] = ldcvt(Ab, r0 + 8, kk + tig + 4);
            }
            #pragma unroll
            for (int j = 0; j < 8; j++) {
                int rn = nw + 8 * j + g;
                bf[j][0] = ldcvt(Bb, rn, kk + tig);
                bf[j][1] = ldcvt(Bb, rn, kk + tig + 4);
            }
            #pragma unroll
            for (int i = 0; i < 4; i++)
                #pragma unroll
                for (int j = 0; j < 8; j++)
                    mma8(acc[i][j], af[i], bf[j]);
        }
        __syncthreads();
    }

    // Epilogue
    #pragma unroll
    for (int i = 0; i < 4; i++) {
        int rA = row0 + mw + 16 * i + g;
        int rB = rA + 8;
        #pragma unroll
        for (int j = 0; j < 8; j++) {
            int c = col0 + nw + 8 * j + 2 * tig;
            float2 v0 = make_float2(acc[i][j][0], acc[i][j][1]);
            float2 v1 = make_float2(acc[i][j][2], acc[i][j][3]);

            if (mode == 0 || mode == 1) {
                float2 bb = *reinterpret_cast<const float2*>(bias + c);
                v0.x += bb.x; v0.y += bb.y;
                v1.x += bb.x; v1.y += bb.y;
                if (mode == 1) {
                    v0.x = 1.0f / (1.0f + expf(-v0.x));
                    v0.y = 1.0f / (1.0f + expf(-v0.y));
                    v1.x = 1.0f / (1.0f + expf(-v1.x));
                    v1.y = 1.0f / (1.0f + expf(-v1.y));
                }
            } else if (mode == 3) {
                long i0 = (long)rA * N + c;
                long i1 = (long)rB * N + c;
                float2 cl0 = *reinterpret_cast<const float2*>(Cls + i0);
                float2 cl1 = *reinterpret_cast<const float2*>(Cls + i1);
                float2 fi0 = *reinterpret_cast<const float2*>(Ifc + i0);
                float2 fi1 = *reinterpret_cast<const float2*>(Ifc + i1);
                v0.x = cl0.x + fi0.x * v0.x;  v0.y = cl0.y + fi0.y * v0.y;
                v1.x = cl1.x + fi1.x * v1.x;  v1.y = cl1.y + fi1.y * v1.y;
            }

            *reinterpret_cast<float2*>(C + (long)rA * N + c) = v0;
            *reinterpret_cast<float2*>(C + (long)rB * N + c) = v1;
        }
    }
}

// ---------------------------------------------------------------------------
// Transpose per batch: in [S,D] -> out [D,S]
// ---------------------------------------------------------------------------
__global__ __launch_bounds__(256)
void transpose_kernel(const float* __restrict__ in, float* __restrict__ out)
{
    __shared__ float t[32][33];
    int bz = blockIdx.z;
    in  += (long)bz * SS * DD;
    out += (long)bz * DD * SS;

    int d0 = blockIdx.x * 32;
    int s0 = blockIdx.y * 32;
    int tx = threadIdx.x & 31;
    int ty = threadIdx.x >> 5;   // 0..7

    #pragma unroll
    for (int i = 0; i < 4; i++) {
        int s = s0 + ty + i * 8;
        t[ty + i * 8][tx] = in[(long)s * DD + d0 + tx];
    }
    __syncthreads();
    #pragma unroll
    for (int i = 0; i < 4; i++) {
        int d = d0 + ty + i * 8;
        out[(long)d * SS + s0 + tx] = t[tx][ty + i * 8];
    }
}

// ---------------------------------------------------------------------------
// Row softmax over S=2048, scaled by (1/sqrt(D))/temperature, in-place.
// ---------------------------------------------------------------------------
__global__ __launch_bounds__(256)
void softmax_kernel(float* __restrict__ sim, const float* __restrict__ temp)
{
    __shared__ float red_max[8];
    __shared__ float red_sum[8];

    long row = blockIdx.x;
    float* p = sim + row * (long)SS;
    int tid  = threadIdx.x;
    int lane = tid & 31;
    int wid  = tid >> 5;

    float s = (1.0f / 32.0f) / (*temp);

    float v[8];
    float mx = -INFINITY;
    #pragma unroll
    for (int i = 0; i < 8; i++) {
        v[i] = p[tid + i * 256] * s;
        mx = fmaxf(mx, v[i]);
    }
    #pragma unroll
    for (int o = 16; o > 0; o >>= 1)
        mx = fmaxf(mx, __shfl_xor_sync(0xffffffffu, mx, o));
    if (lane == 0) red_max[wid] = mx;
    __syncthreads();
    mx = red_max[0];
    #pragma unroll
    for (int w = 1; w < 8; w++) mx = fmaxf(mx, red_max[w]);

    float sum = 0.0f;
    #pragma unroll
    for (int i = 0; i < 8; i++) {
        v[i] = expf(v[i] - mx);
        sum += v[i];
    }
    #pragma unroll
    for (int o = 16; o > 0; o >>= 1)
        sum += __shfl_xor_sync(0xffffffffu, sum, o);
    if (lane == 0) red_sum[wid] = sum;
    __syncthreads();
    sum = 0.0f;
    #pragma unroll
    for (int w = 0; w < 8; w++) sum += red_sum[w];

    float inv = 1.0f / sum;
    #pragma unroll
    for (int i = 0; i < 8; i++)
        p[tid + i * 256] = v[i] * inv;
}

// ---------------------------------------------------------------------------
extern "C" void kernel_launch(void* const* d_in, const int* in_sizes, int n_in,
                              void* d_out, int out_size)
{
    const float* classical = (const float*)d_in[0];
    const float* quantum   = (const float*)d_in[1];
    const float* Wc        = (const float*)d_in[2];
    const float* bc        = (const float*)d_in[3];
    const float* Wq        = (const float*)d_in[4];
    const float* bq        = (const float*)d_in[5];
    const float* Wg        = (const float*)d_in[6];
    const float* bg        = (const float*)d_in[7];
    const float* temp      = (const float*)d_in[8];
    float* out             = (float*)d_out;

    float *cproj, *qproj, *iface, *qT, *sim;
    cudaGetSymbolAddress((void**)&cproj, g_cproj);
    cudaGetSymbolAddress((void**)&qproj, g_qproj);
    cudaGetSymbolAddress((void**)&iface, g_iface);
    cudaGetSymbolAddress((void**)&qT,    g_qT);
    cudaGetSymbolAddress((void**)&sim,   g_sim);

    cudaFuncSetAttribute(gemm_tc_kernel,
                         cudaFuncAttributeMaxDynamicSharedMemorySize, SM_TOTAL);

    dim3 blk(128);

    // 0) qT[b] = quantum[b]^T  [D,S]
    transpose_kernel<<<dim3(DD/32, SS/32, BB), 256>>>(quantum, qT);

    // 1) c_proj = classical @ Wc^T + bc    [8192,1024]
    gemm_tc_kernel<<<dim3(DD/128, MS/128, 1), blk, SM_TOTAL>>>(
        classical, nullptr, Wc, bc, nullptr, nullptr, cproj,
        DD, DD, DD, DD, 0, 0, 0, 0);

    // 2) q_proj = quantum @ Wq^T + bq
    gemm_tc_kernel<<<dim3(DD/128, MS/128, 1), blk, SM_TOTAL>>>(
        quantum, nullptr, Wq, bq, nullptr, nullptr, qproj,
        DD, DD, DD, DD, 0, 0, 0, 0);

    // 3) interface = sigmoid([c_proj|q_proj] @ Wg^T + bg), K=2048 split at 1024
    gemm_tc_kernel<<<dim3(DD/128, MS/128, 1), blk, SM_TOTAL>>>(
        cproj, qproj, Wg, bg, nullptr, nullptr, iface,
        DD, 2*DD, DD, DD, 0, 0, 0, 1);

    // 4) sim[b] = c_proj[b] @ q_proj[b]^T  (raw; scale folded into softmax)
    gemm_tc_kernel<<<dim3(SS/128, SS/128, BB), blk, SM_TOTAL>>>(
        cproj, nullptr, qproj, nullptr, nullptr, nullptr, sim,
        SS, DD, DD, DD,
        (long)SS*DD, (long)SS*DD, (long)SS*SS, 2);

    // 5) softmax rows
    softmax_kernel<<<BB*SS, 256>>>(sim, temp);

    // 6) out = classical + iface * (attn[b] @ qT[b]^T)
    gemm_tc_kernel<<<dim3(DD/128, SS/128, BB), blk, SM_TOTAL>>>(
        sim, nullptr, qT, nullptr, classical, iface, out,
        DD, SS, SS, SS,
        (long)SS*SS, (long)DD*SS, (long)SS*DD, 3);
}

// round 5
// speedup vs baseline: 4.2736x; 1.0283x over previous
#include <cuda_runtime.h>
#include <math.h>
#include <stdint.h>

// Problem constants
#define BB 4
#define SS 2048
#define DD 1024
#define MS (BB*SS)          // 8192 rows

#define KC  32              // K floats per chunk (128B rows in smem)
#define SM_BUF 16384        // one 128x32 fp32 tile
#define NSTAGE 3
#define SM_STAGE (2*SM_BUF)
#define SM_TOTAL (NSTAGE*SM_STAGE)   // 96 KB

// Scratch (no allocations allowed -> device globals)
__device__ float g_cproj[MS*DD];           // 32 MB (tf32-rounded at store)
__device__ float g_qproj[MS*DD];           // 32 MB (tf32-rounded at store)
__device__ float g_iface[MS*DD];           // 32 MB
__device__ float g_qT[(size_t)BB*DD*SS];   // 32 MB (tf32-rounded)
__device__ float g_sim[(size_t)BB*SS*SS];  // 64 MB (tf32-rounded after softmax)
// tf32-rounded copies of raw inputs
__device__ float g_clsr[MS*DD];            // 32 MB
__device__ float g_qr[MS*DD];              // 32 MB
__device__ float g_Wcr[DD*DD];             // 4 MB
__device__ float g_Wqr[DD*DD];             // 4 MB
__device__ float g_Wgr[DD*2*DD];           // 8 MB

// ---------------------------------------------------------------------------
__device__ __forceinline__ uint32_t smem_u32(const void* p) {
    uint32_t a;
    asm("{ .reg .u64 t; cvta.to.shared.u64 t, %1; cvt.u32.u64 %0, t; }" : "=r"(a) : "l"(p));
    return a;
}
__device__ __forceinline__ float round_tf32(float x) {
    uint32_t t;
    asm("cvt.rna.tf32.f32 %0, %1;" : "=r"(t) : "f"(x));
    return __uint_as_float(t);
}

#define CP_COMMIT() asm volatile("cp.async.commit_group;" ::: "memory")
#define CP_WAIT(n)  asm volatile("cp.async.wait_group %0;" :: "n"(n) : "memory")

// Load one 128-row x 32-float chunk, global->smem via cp.async with XOR swizzle.
// 128 threads, 8 float4 each. Swizzle: float4 seg s of row r stored at s ^ (r&7).
__device__ __forceinline__ void load_chunk(const float* __restrict__ src, int ld,
                                           int row0, int kc, uint32_t sbuf, int tid) {
    #pragma unroll
    for (int i = 0; i < 8; i++) {
        int idx = i * 128 + tid;
        int row = idx >> 3;
        int seg = idx & 7;
        const float* gp = src + (long)(row0 + row) * ld + kc + seg * 4;
        uint32_t off = sbuf + row * 128 + ((seg ^ (row & 7)) << 4);
        asm volatile("cp.async.cg.shared.global [%0], [%1], 16;" :: "r"(off), "l"(gp));
    }
}

__device__ __forceinline__ uint32_t lds32(uint32_t addr) {
    uint32_t v;
    asm volatile("ld.shared.b32 %0, [%1];" : "=r"(v) : "r"(addr));
    return v;
}

__device__ __forceinline__ void mma8(float* c, const uint32_t* a, const uint32_t* b) {
    asm volatile("mma.sync.aligned.m16n8k8.row.col.f32.tf32.tf32.f32 "
                 "{%0,%1,%2,%3}, {%4,%5,%6,%7}, {%8,%9}, {%0,%1,%2,%3};"
                 : "+f"(c[0]), "+f"(c[1]), "+f"(c[2]), "+f"(c[3])
                 : "r"(a[0]), "r"(a[1]), "r"(a[2]), "r"(a[3]), "r"(b[0]), "r"(b[1]));
}

// ---------------------------------------------------------------------------
// NT tf32 tensor-core GEMM: C[m,n] = epi( sum_k A[m,k] * B[n,k] )
// Operands MUST already be tf32-rounded (low 13 mantissa bits zero).
// A-concat: chunk k >= Ksplit reads A2[m, k-Ksplit] (same lda).
// mode 0: +bias, round-tf32 store   1: sigmoid(+bias)   2: raw   3: Cls+Ifc*acc
// ---------------------------------------------------------------------------
__global__ __launch_bounds__(128, 2)
void gemm_tc_kernel(const float* __restrict__ A,
                    const float* __restrict__ A2,
                    const float* __restrict__ B,
                    const float* __restrict__ bias,
                    const float* __restrict__ Cls,
                    const float* __restrict__ Ifc,
                    float* __restrict__ C,
                    int N, int K, int Ksplit, int lda,
                    long As_batch, long Bs_batch, long Cs_batch,
                    int mode)
{
    extern __shared__ char smem[];
    uint32_t sb = smem_u32(smem);

    int tid  = threadIdx.x;
    int wid  = tid >> 5;
    int lane = tid & 31;
    int g    = lane >> 2;      // 0..7
    int tig  = lane & 3;       // 0..3
    int mw   = (wid >> 1) * 64;
    int nw   = (wid & 1) * 64;

    int bz = blockIdx.z;
    A += bz * As_batch;
    if (A2) A2 += bz * As_batch;
    B += bz * Bs_batch;
    if (Cls) Cls += bz * Cs_batch;
    if (Ifc) Ifc += bz * Cs_batch;
    C += bz * Cs_batch;

    int row0 = blockIdx.y * 128;
    int col0 = blockIdx.x * 128;

    // Per-thread swizzled column offsets: all fragment rows have row&7 == g,
    // so addr = base + row*128 + sw[col>>2], sw[c2] = ((c2^g)<<4) | (tig<<2).
    uint32_t sw[8];
    #pragma unroll
    for (int c2 = 0; c2 < 8; c2++) sw[c2] = (uint32_t)(((c2 ^ g) << 4) | (tig << 2));

    float acc[4][8][4];
    #pragma unroll
    for (int i = 0; i < 4; i++)
        #pragma unroll
        for (int j = 0; j < 8; j++)
            #pragma unroll
            for (int q = 0; q < 4; q++) acc[i][j][q] = 0.0f;

    const int NC = K / KC;

    // prologue: chunks 0,1 -> stages 0,1
    #pragma unroll
    for (int p = 0; p < 2; p++) {
        int kt = p * KC;
        const float* Ap; int kA;
        if (kt < Ksplit) { Ap = A;  kA = kt; }
        else             { Ap = A2; kA = kt - Ksplit; }
        uint32_t stg = sb + p * SM_STAGE;
        load_chunk(Ap, lda, row0, kA, stg, tid);
        load_chunk(B,  K,   col0, kt, stg + SM_BUF, tid);
        CP_COMMIT();
    }

    int stage = 0;
    for (int ch = 0; ch < NC; ch++) {
        if (ch + 2 < NC) {
            int kt = (ch + 2) * KC;
            const float* Ap; int kA;
            if (kt < Ksplit) { Ap = A;  kA = kt; }
            else             { Ap = A2; kA = kt - Ksplit; }
            int ns = stage + 2; if (ns >= NSTAGE) ns -= NSTAGE;
            uint32_t stg = sb + ns * SM_STAGE;
            load_chunk(Ap, lda, row0, kA, stg, tid);
            load_chunk(B,  K,   col0, kt, stg + SM_BUF, tid);
            CP_COMMIT();
            CP_WAIT(2);
        } else if (ch + 1 < NC) {
            CP_WAIT(1);
        } else {
            CP_WAIT(0);
        }
        __syncthreads();

        uint32_t Ab = sb + stage * SM_STAGE;
        uint32_t Bb = Ab + SM_BUF;
        uint32_t At = Ab + (uint32_t)(mw + g) * 128;
        uint32_t Bt = Bb + (uint32_t)(nw + g) * 128;

        #pragma unroll
        for (int ks = 0; ks < 4; ks++) {
            uint32_t s0 = sw[2 * ks], s1 = sw[2 * ks + 1];
            uint32_t af[4][4], bf[8][2];
            #pragma unroll
            for (int i = 0; i < 4; i++) {
                uint32_t p = At + i * 2048;
                af[i][0] = lds32(p + s0);
                af[i][1] = lds32(p + 1024 + s0);
                af[i][2] = lds32(p + s1);
                af[i][3] = lds32(p + 1024 + s1);
            }
            #pragma unroll
            for (int j = 0; j < 8; j++) {
                uint32_t p = Bt + j * 1024;
                bf[j][0] = lds32(p + s0);
                bf[j][1] = lds32(p + s1);
            }
            #pragma unroll
            for (int i = 0; i < 4; i++)
                #pragma unroll
                for (int j = 0; j < 8; j++)
                    mma8(acc[i][j], af[i], bf[j]);
        }
        __syncthreads();

        stage++; if (stage >= NSTAGE) stage = 0;
    }

    // Epilogue
    #pragma unroll
    for (int i = 0; i < 4; i++) {
        int rA = row0 + mw + 16 * i + g;
        int rB = rA + 8;
        #pragma unroll
        for (int j = 0; j < 8; j++) {
            int c = col0 + nw + 8 * j + 2 * tig;
            float2 v0 = make_float2(acc[i][j][0], acc[i][j][1]);
            float2 v1 = make_float2(acc[i][j][2], acc[i][j][3]);

            if (mode == 0 || mode == 1) {
                float2 bb = *reinterpret_cast<const float2*>(bias + c);
                v0.x += bb.x; v0.y += bb.y;
                v1.x += bb.x; v1.y += bb.y;
                if (mode == 1) {
                    v0.x = 1.0f / (1.0f + expf(-v0.x));
                    v0.y = 1.0f / (1.0f + expf(-v0.y));
                    v1.x = 1.0f / (1.0f + expf(-v1.x));
                    v1.y = 1.0f / (1.0f + expf(-v1.y));
                } else {
                    // mode 0 output feeds later GEMMs: store tf32-rounded
                    v0.x = round_tf32(v0.x); v0.y = round_tf32(v0.y);
                    v1.x = round_tf32(v1.x); v1.y = round_tf32(v1.y);
                }
            } else if (mode == 3) {
                long i0 = (long)rA * N + c;
                long i1 = (long)rB * N + c;
                float2 cl0 = *reinterpret_cast<const float2*>(Cls + i0);
                float2 cl1 = *reinterpret_cast<const float2*>(Cls + i1);
                float2 fi0 = *reinterpret_cast<const float2*>(Ifc + i0);
                float2 fi1 = *reinterpret_cast<const float2*>(Ifc + i1);
                v0.x = cl0.x + fi0.x * v0.x;  v0.y = cl0.y + fi0.y * v0.y;
                v1.x = cl1.x + fi1.x * v1.x;  v1.y = cl1.y + fi1.y * v1.y;
            }

            *reinterpret_cast<float2*>(C + (long)rA * N + c) = v0;
            *reinterpret_cast<float2*>(C + (long)rB * N + c) = v1;
        }
    }
}

// ---------------------------------------------------------------------------
// Elementwise tf32 rounding pass (float4 grid-stride)
// ---------------------------------------------------------------------------
__global__ __launch_bounds__(256)
void round_kernel(const float* __restrict__ in, float* __restrict__ out, long n4)
{
    long i = (long)blockIdx.x * blockDim.x + threadIdx.x;
    long stride = (long)gridDim.x * blockDim.x;
    for (; i < n4; i += stride) {
        float4 v = reinterpret_cast<const float4*>(in)[i];
        v.x = round_tf32(v.x); v.y = round_tf32(v.y);
        v.z = round_tf32(v.z); v.w = round_tf32(v.w);
        reinterpret_cast<float4*>(out)[i] = v;
    }
}

// ---------------------------------------------------------------------------
// Transpose per batch: in [S,D] -> out [D,S], tf32-rounded
// ---------------------------------------------------------------------------
__global__ __launch_bounds__(256)
void transpose_kernel(const float* __restrict__ in, float* __restrict__ out)
{
    __shared__ float t[32][33];
    int bz = blockIdx.z;
    in  += (long)bz * SS * DD;
    out += (long)bz * DD * SS;

    int d0 = blockIdx.x * 32;
    int s0 = blockIdx.y * 32;
    int tx = threadIdx.x & 31;
    int ty = threadIdx.x >> 5;   // 0..7

    #pragma unroll
    for (int i = 0; i < 4; i++) {
        int s = s0 + ty + i * 8;
        t[ty + i * 8][tx] = round_tf32(in[(long)s * DD + d0 + tx]);
    }
    __syncthreads();
    #pragma unroll
    for (int i = 0; i < 4; i++) {
        int d = d0 + ty + i * 8;
        out[(long)d * SS + s0 + tx] = t[tx][ty + i * 8];
    }
}

// ---------------------------------------------------------------------------
// Row softmax over S=2048, scaled by (1/sqrt(D))/temperature, in-place,
// output tf32-rounded (it feeds the transfer GEMM).
// ---------------------------------------------------------------------------
__global__ __launch_bounds__(256)
void softmax_kernel(float* __restrict__ sim, const float* __restrict__ temp)
{
    __shared__ float red_max[8];
    __shared__ float red_sum[8];

    long row = blockIdx.x;
    float* p = sim + row * (long)SS;
    int tid  = threadIdx.x;
    int lane = tid & 31;
    int wid  = tid >> 5;

    float s = (1.0f / 32.0f) / (*temp);

    float v[8];
    float mx = -INFINITY;
    #pragma unroll
    for (int i = 0; i < 8; i++) {
        v[i] = p[tid + i * 256] * s;
        mx = fmaxf(mx, v[i]);
    }
    #pragma unroll
    for (int o = 16; o > 0; o >>= 1)
        mx = fmaxf(mx, __shfl_xor_sync(0xffffffffu, mx, o));
    if (lane == 0) red_max[wid] = mx;
    __syncthreads();
    mx = red_max[0];
    #pragma unroll
    for (int w = 1; w < 8; w++) mx = fmaxf(mx, red_max[w]);

    float sum = 0.0f;
    #pragma unroll
    for (int i = 0; i < 8; i++) {
        v[i] = expf(v[i] - mx);
        sum += v[i];
    }
    #pragma unroll
    for (int o = 16; o > 0; o >>= 1)
        sum += __shfl_xor_sync(0xffffffffu, sum, o);
    if (lane == 0) red_sum[wid] = sum;
    __syncthreads();
    sum = 0.0f;
    #pragma unroll
    for (int w = 0; w < 8; w++) sum += red_sum[w];

    float inv = 1.0f / sum;
    #pragma unroll
    for (int i = 0; i < 8; i++)
        p[tid + i * 256] = round_tf32(v[i] * inv);
}

// ---------------------------------------------------------------------------
extern "C" void kernel_launch(void* const* d_in, const int* in_sizes, int n_in,
                              void* d_out, int out_size)
{
    const float* classical = (const float*)d_in[0];
    const float* quantum   = (const float*)d_in[1];
    const float* Wc        = (const float*)d_in[2];
    const float* bc        = (const float*)d_in[3];
    const float* Wq        = (const float*)d_in[4];
    const float* bq        = (const float*)d_in[5];
    const float* Wg        = (const float*)d_in[6];
    const float* bg        = (const float*)d_in[7];
    const float* temp      = (const float*)d_in[8];
    float* out             = (float*)d_out;

    float *cproj, *qproj, *iface, *qT, *sim, *clsr, *qr, *Wcr, *Wqr, *Wgr;
    cudaGetSymbolAddress((void**)&cproj, g_cproj);
    cudaGetSymbolAddress((void**)&qproj, g_qproj);
    cudaGetSymbolAddress((void**)&iface, g_iface);
    cudaGetSymbolAddress((void**)&qT,    g_qT);
    cudaGetSymbolAddress((void**)&sim,   g_sim);
    cudaGetSymbolAddress((void**)&clsr,  g_clsr);
    cudaGetSymbolAddress((void**)&qr,    g_qr);
    cudaGetSymbolAddress((void**)&Wcr,   g_Wcr);
    cudaGetSymbolAddress((void**)&Wqr,   g_Wqr);
    cudaGetSymbolAddress((void**)&Wgr,   g_Wgr);

    cudaFuncSetAttribute(gemm_tc_kernel,
                         cudaFuncAttributeMaxDynamicSharedMemorySize, SM_TOTAL);

    dim3 blk(128);

    // Pre-round raw inputs to tf32 format
    round_kernel<<<2048, 256>>>(classical, clsr, (long)MS*DD/4);
    round_kernel<<<2048, 256>>>(quantum,   qr,   (long)MS*DD/4);
    round_kernel<<<1024, 256>>>(Wc,        Wcr,  (long)DD*DD/4);
    round_kernel<<<1024, 256>>>(Wq,        Wqr,  (long)DD*DD/4);
    round_kernel<<<1024, 256>>>(Wg,        Wgr,  (long)DD*2*DD/4);

    // 0) qT[b] = quantum[b]^T  [D,S], tf32-rounded
    transpose_kernel<<<dim3(DD/32, SS/32, BB), 256>>>(quantum, qT);

    // 1) c_proj = classical @ Wc^T + bc    [8192,1024], tf32-rounded store
    gemm_tc_kernel<<<dim3(DD/128, MS/128, 1), blk, SM_TOTAL>>>(
        clsr, nullptr, Wcr, bc, nullptr, nullptr, cproj,
        DD, DD, DD, DD, 0, 0, 0, 0);

    // 2) q_proj = quantum @ Wq^T + bq, tf32-rounded store
    gemm_tc_kernel<<<dim3(DD/128, MS/128, 1), blk, SM_TOTAL>>>(
        qr, nullptr, Wqr, bq, nullptr, nullptr, qproj,
        DD, DD, DD, DD, 0, 0, 0, 0);

    // 3) interface = sigmoid([c_proj|q_proj] @ Wg^T + bg), K=2048 split at 1024
    gemm_tc_kernel<<<dim3(DD/128, MS/128, 1), blk, SM_TOTAL>>>(
        cproj, qproj, Wgr, bg, nullptr, nullptr, iface,
        DD, 2*DD, DD, DD, 0, 0, 0, 1);

    // 4) sim[b] = c_proj[b] @ q_proj[b]^T  (raw; scale folded into softmax)
    gemm_tc_kernel<<<dim3(SS/128, SS/128, BB), blk, SM_TOTAL>>>(
        cproj, nullptr, qproj, nullptr, nullptr, nullptr, sim,
        SS, DD, DD, DD,
        (long)SS*DD, (long)SS*DD, (long)SS*SS, 2);

    // 5) softmax rows (tf32-rounded output)
    softmax_kernel<<<BB*SS, 256>>>(sim, temp);

    // 6) out = classical + iface * (attn[b] @ qT[b]^T)
    gemm_tc_kernel<<<dim3(DD/128, SS/128, BB), blk, SM_TOTAL>>>(
        sim, nullptr, qT, nullptr, classical, iface, out,
        DD, SS, SS, SS,
        (long)SS*SS, (long)DD*SS, (long)SS*DD, 3);
}

// round 6
// speedup vs baseline: 7.0757x; 1.6557x over previous
#include <cuda_runtime.h>
#include <cuda_bf16.h>
#include <math.h>
#include <stdint.h>

// Problem constants
#define BB 4
#define SS 2048
#define DD 1024
#define MS (BB*SS)          // 8192 rows

#define KC  64              // K bf16 elements per chunk (= 128B smem rows)
#define SM_BUF 16384        // one 128x64 bf16 tile
#define NSTAGE 3
#define SM_STAGE (2*SM_BUF)
#define SM_TOTAL (NSTAGE*SM_STAGE)   // 96 KB

// Scratch (no allocations allowed -> device globals)
__device__ __nv_bfloat16 g_cls_bf[MS*DD];            // 16 MB
__device__ __nv_bfloat16 g_q_bf[MS*DD];              // 16 MB
__device__ __nv_bfloat16 g_Wc_bf[DD*DD];             // 2 MB
__device__ __nv_bfloat16 g_Wq_bf[DD*DD];             // 2 MB
__device__ __nv_bfloat16 g_Wg_bf[DD*2*DD];           // 4 MB
__device__ __nv_bfloat16 g_cproj[MS*DD];             // 16 MB
__device__ __nv_bfloat16 g_qproj[MS*DD];             // 16 MB
__device__ __nv_bfloat16 g_qT[(size_t)BB*DD*SS];     // 16 MB
__device__ __nv_bfloat16 g_attn[(size_t)BB*SS*SS];   // 32 MB
__device__ float g_iface[MS*DD];                     // 32 MB
__device__ float g_sim[(size_t)BB*SS*SS];            // 64 MB

// ---------------------------------------------------------------------------
__device__ __forceinline__ uint32_t smem_u32(const void* p) {
    uint32_t a;
    asm("{ .reg .u64 t; cvta.to.shared.u64 t, %1; cvt.u32.u64 %0, t; }" : "=r"(a) : "l"(p));
    return a;
}
__device__ __forceinline__ uint32_t pack_bf16(float lo, float hi) {
    uint32_t u;
    asm("cvt.rn.bf16x2.f32 %0, %1, %2;" : "=r"(u) : "f"(hi), "f"(lo));
    return u;
}

#define CP_COMMIT() asm volatile("cp.async.commit_group;" ::: "memory")
#define CP_WAIT(n)  asm volatile("cp.async.wait_group %0;" :: "n"(n) : "memory")

// Load one 128-row x 64-bf16 chunk, global->smem via cp.async, XOR swizzle.
// 128 threads, 8 x 16B each. Seg s (16B) of row r stored at s ^ (r&7).
__device__ __forceinline__ void load_chunk(const __nv_bfloat16* __restrict__ src, int ld,
                                           int row0, int kc, uint32_t sbuf, int tid) {
    #pragma unroll
    for (int i = 0; i < 8; i++) {
        int idx = i * 128 + tid;
        int row = idx >> 3;
        int seg = idx & 7;
        const __nv_bfloat16* gp = src + (long)(row0 + row) * ld + kc + seg * 8;
        uint32_t off = sbuf + row * 128 + ((seg ^ (row & 7)) << 4);
        asm volatile("cp.async.cg.shared.global [%0], [%1], 16;" :: "r"(off), "l"(gp));
    }
}

#define LDSM4(d, addr) \
    asm volatile("ldmatrix.sync.aligned.m8n8.x4.shared.b16 {%0,%1,%2,%3}, [%4];" \
        : "=r"((d)[0]), "=r"((d)[1]), "=r"((d)[2]), "=r"((d)[3]) : "r"(addr))

__device__ __forceinline__ void mma16(float* c, const uint32_t* a, const uint32_t* b) {
    asm volatile("mma.sync.aligned.m16n8k16.row.col.f32.bf16.bf16.f32 "
                 "{%0,%1,%2,%3}, {%4,%5,%6,%7}, {%8,%9}, {%0,%1,%2,%3};"
                 : "+f"(c[0]), "+f"(c[1]), "+f"(c[2]), "+f"(c[3])
                 : "r"(a[0]), "r"(a[1]), "r"(a[2]), "r"(a[3]), "r"(b[0]), "r"(b[1]));
}

// ---------------------------------------------------------------------------
// NT bf16 tensor-core GEMM: acc[m,n] = sum_k A[m,k] * B[n,k]  (fp32 accum)
// A-concat: chunk k >= Ksplit reads A2[m, k-Ksplit] (same lda).
// mode 0: bf16 store of (acc+bias)   1: fp32 sigmoid(acc+bias)
// mode 2: fp32 raw                   3: fp32 Cls + Ifc*acc
// ---------------------------------------------------------------------------
__global__ __launch_bounds__(128, 2)
void gemm_bf_kernel(const __nv_bfloat16* __restrict__ A,
                    const __nv_bfloat16* __restrict__ A2,
                    const __nv_bfloat16* __restrict__ B,
                    const float* __restrict__ bias,
                    const float* __restrict__ Cls,
                    const float* __restrict__ Ifc,
                    void* __restrict__ Cout,
                    int N, int K, int Ksplit, int lda,
                    long As_batch, long Bs_batch, long Cs_batch,
                    int mode)
{
    extern __shared__ char smem[];
    uint32_t sb = smem_u32(smem);

    int tid  = threadIdx.x;
    int wid  = tid >> 5;
    int lane = tid & 31;
    int g    = lane >> 2;      // 0..7
    int tig  = lane & 3;       // 0..3
    int mw   = (wid >> 1) * 64;
    int nw   = (wid & 1) * 64;

    int bz = blockIdx.z;
    A += bz * As_batch;
    if (A2) A2 += bz * As_batch;
    B += bz * Bs_batch;
    if (Cls) Cls += bz * Cs_batch;
    if (Ifc) Ifc += bz * Cs_batch;

    int row0 = blockIdx.y * 128;
    int col0 = blockIdx.x * 128;

    // ldmatrix per-thread addressing: lane t serves matrix q=t>>3, row r=t&7.
    // Matrix q: row offset ql*8 (ql=q&1), k-half qh (qh=q>>1).
    int r  = lane & 7;
    int q  = lane >> 3;
    int ql = q & 1;
    int qh = q >> 1;
    uint32_t segoff[4];
    #pragma unroll
    for (int ks = 0; ks < 4; ks++)
        segoff[ks] = (uint32_t)((((2 * ks + qh) ^ r) << 4));
    uint32_t Arow = (uint32_t)((mw + ql * 8 + r) * 128);
    uint32_t Brow = (uint32_t)((nw + ql * 8 + r) * 128);

    float acc[4][8][4];
    #pragma unroll
    for (int i = 0; i < 4; i++)
        #pragma unroll
        for (int j = 0; j < 8; j++)
            #pragma unroll
            for (int p = 0; p < 4; p++) acc[i][j][p] = 0.0f;

    const int NC = K / KC;

    // prologue: chunks 0,1 -> stages 0,1
    #pragma unroll
    for (int p = 0; p < 2; p++) {
        int kt = p * KC;
        const __nv_bfloat16* Ap; int kA;
        if (kt < Ksplit) { Ap = A;  kA = kt; }
        else             { Ap = A2; kA = kt - Ksplit; }
        uint32_t stg = sb + p * SM_STAGE;
        load_chunk(Ap, lda, row0, kA, stg, tid);
        load_chunk(B,  K,   col0, kt, stg + SM_BUF, tid);
        CP_COMMIT();
    }

    int stage = 0;
    for (int ch = 0; ch < NC; ch++) {
        if (ch + 2 < NC) {
            int kt = (ch + 2) * KC;
            const __nv_bfloat16* Ap; int kA;
            if (kt < Ksplit) { Ap = A;  kA = kt; }
            else             { Ap = A2; kA = kt - Ksplit; }
            int ns = stage + 2; if (ns >= NSTAGE) ns -= NSTAGE;
            uint32_t stg = sb + ns * SM_STAGE;
            load_chunk(Ap, lda, row0, kA, stg, tid);
            load_chunk(B,  K,   col0, kt, stg + SM_BUF, tid);
            CP_COMMIT();
            CP_WAIT(2);
        } else if (ch + 1 < NC) {
            CP_WAIT(1);
        } else {
            CP_WAIT(0);
        }
        __syncthreads();

        uint32_t At = sb + stage * SM_STAGE + Arow;
        uint32_t Bt = sb + stage * SM_STAGE + SM_BUF + Brow;

        #pragma unroll
        for (int ks = 0; ks < 4; ks++) {          // 4 x k16 = 64
            uint32_t so = segoff[ks];
            uint32_t af[4][4];
            #pragma unroll
            for (int i = 0; i < 4; i++)
                LDSM4(af[i], At + i * 2048 + so);
            uint32_t bf[8][2];
            #pragma unroll
            for (int j2 = 0; j2 < 4; j2++) {
                uint32_t t[4];
                LDSM4(t, Bt + j2 * 2048 + so);
                bf[2 * j2][0]     = t[0];
                bf[2 * j2 + 1][0] = t[1];
                bf[2 * j2][1]     = t[2];
                bf[2 * j2 + 1][1] = t[3];
            }
            #pragma unroll
            for (int i = 0; i < 4; i++)
                #pragma unroll
                for (int j = 0; j < 8; j++)
                    mma16(acc[i][j], af[i], bf[j]);
        }
        __syncthreads();

        stage++; if (stage >= NSTAGE) stage = 0;
    }

    // Epilogue: c0,c1 at (row g, cols 2tig..), c2,c3 at row g+8
    #pragma unroll
    for (int i = 0; i < 4; i++) {
        int rA = row0 + mw + 16 * i + g;
        int rB = rA + 8;
        #pragma unroll
        for (int j = 0; j < 8; j++) {
            int c = col0 + nw + 8 * j + 2 * tig;
            float2 v0 = make_float2(acc[i][j][0], acc[i][j][1]);
            float2 v1 = make_float2(acc[i][j][2], acc[i][j][3]);

            if (mode == 0) {
                float2 bb = *reinterpret_cast<const float2*>(bias + c);
                __nv_bfloat16* Cb = (__nv_bfloat16*)Cout + bz * Cs_batch;
                *reinterpret_cast<uint32_t*>(Cb + (long)rA * N + c) =
                    pack_bf16(v0.x + bb.x, v0.y + bb.y);
                *reinterpret_cast<uint32_t*>(Cb + (long)rB * N + c) =
                    pack_bf16(v1.x + bb.x, v1.y + bb.y);
            } else {
                float* Cf = (float*)Cout + bz * Cs_batch;
                if (mode == 1) {
                    float2 bb = *reinterpret_cast<const float2*>(bias + c);
                    v0.x = 1.0f / (1.0f + expf(-(v0.x + bb.x)));
                    v0.y = 1.0f / (1.0f + expf(-(v0.y + bb.y)));
                    v1.x = 1.0f / (1.0f + expf(-(v1.x + bb.x)));
                    v1.y = 1.0f / (1.0f + expf(-(v1.y + bb.y)));
                } else if (mode == 3) {
                    long i0 = (long)rA * N + c;
                    long i1 = (long)rB * N + c;
                    float2 cl0 = *reinterpret_cast<const float2*>(Cls + i0);
                    float2 cl1 = *reinterpret_cast<const float2*>(Cls + i1);
                    float2 fi0 = *reinterpret_cast<const float2*>(Ifc + i0);
                    float2 fi1 = *reinterpret_cast<const float2*>(Ifc + i1);
                    v0.x = cl0.x + fi0.x * v0.x;  v0.y = cl0.y + fi0.y * v0.y;
                    v1.x = cl1.x + fi1.x * v1.x;  v1.y = cl1.y + fi1.y * v1.y;
                }
                *reinterpret_cast<float2*>(Cf + (long)rA * N + c) = v0;
                *reinterpret_cast<float2*>(Cf + (long)rB * N + c) = v1;
            }
        }
    }
}

// ---------------------------------------------------------------------------
// fp32 -> bf16 conversion (float4 grid-stride)
// ---------------------------------------------------------------------------
__global__ __launch_bounds__(256)
void tobf16_kernel(const float* __restrict__ in, __nv_bfloat16* __restrict__ out, long n4)
{
    long i = (long)blockIdx.x * blockDim.x + threadIdx.x;
    long stride = (long)gridDim.x * blockDim.x;
    for (; i < n4; i += stride) {
        float4 v = reinterpret_cast<const float4*>(in)[i];
        uint2 o;
        o.x = pack_bf16(v.x, v.y);
        o.y = pack_bf16(v.z, v.w);
        reinterpret_cast<uint2*>(out)[i] = o;
    }
}

// ---------------------------------------------------------------------------
// Transpose per batch: fp32 in [S,D] -> bf16 out [D,S]
// ---------------------------------------------------------------------------
__global__ __launch_bounds__(256)
void transpose_kernel(const float* __restrict__ in, __nv_bfloat16* __restrict__ out)
{
    __shared__ float t[32][33];
    int bz = blockIdx.z;
    in  += (long)bz * SS * DD;
    out += (long)bz * DD * SS;

    int d0 = blockIdx.x * 32;
    int s0 = blockIdx.y * 32;
    int tx = threadIdx.x & 31;
    int ty = threadIdx.x >> 5;   // 0..7

    #pragma unroll
    for (int i = 0; i < 4; i++) {
        int s = s0 + ty + i * 8;
        t[ty + i * 8][tx] = in[(long)s * DD + d0 + tx];
    }
    __syncthreads();
    #pragma unroll
    for (int i = 0; i < 4; i++) {
        int d = d0 + ty + i * 8;
        out[(long)d * SS + s0 + tx] = __float2bfloat16(t[tx][ty + i * 8]);
    }
}

// ---------------------------------------------------------------------------
// Row softmax over S=2048, scale (1/sqrt(D))/T; fp32 in, bf16 out.
// ---------------------------------------------------------------------------
__global__ __launch_bounds__(256)
void softmax_kernel(const float* __restrict__ sim, __nv_bfloat16* __restrict__ attn,
                    const float* __restrict__ temp)
{
    __shared__ float red_max[8];
    __shared__ float red_sum[8];

    long row = blockIdx.x;
    const float* p = sim + row * (long)SS;
    __nv_bfloat16* po = attn + row * (long)SS;
    int tid  = threadIdx.x;
    int lane = tid & 31;
    int wid  = tid >> 5;

    float s = (1.0f / 32.0f) / (*temp);

    float v[8];
    float mx = -INFINITY;
    #pragma unroll
    for (int i = 0; i < 8; i++) {
        v[i] = p[tid + i * 256] * s;
        mx = fmaxf(mx, v[i]);
    }
    #pragma unroll
    for (int o = 16; o > 0; o >>= 1)
        mx = fmaxf(mx, __shfl_xor_sync(0xffffffffu, mx, o));
    if (lane == 0) red_max[wid] = mx;
    __syncthreads();
    mx = red_max[0];
    #pragma unroll
    for (int w = 1; w < 8; w++) mx = fmaxf(mx, red_max[w]);

    float sum = 0.0f;
    #pragma unroll
    for (int i = 0; i < 8; i++) {
        v[i] = expf(v[i] - mx);
        sum += v[i];
    }
    #pragma unroll
    for (int o = 16; o > 0; o >>= 1)
        sum += __shfl_xor_sync(0xffffffffu, sum, o);
    if (lane == 0) red_sum[wid] = sum;
    __syncthreads();
    sum = 0.0f;
    #pragma unroll
    for (int w = 0; w < 8; w++) sum += red_sum[w];

    float inv = 1.0f / sum;
    #pragma unroll
    for (int i = 0; i < 8; i++)
        po[tid + i * 256] = __float2bfloat16(v[i] * inv);
}

// ---------------------------------------------------------------------------
extern "C" void kernel_launch(void* const* d_in, const int* in_sizes, int n_in,
                              void* d_out, int out_size)
{
    const float* classical = (const float*)d_in[0];
    const float* quantum   = (const float*)d_in[1];
    const float* Wc        = (const float*)d_in[2];
    const float* bc        = (const float*)d_in[3];
    const float* Wq        = (const float*)d_in[4];
    const float* bq        = (const float*)d_in[5];
    const float* Wg        = (const float*)d_in[6];
    const float* bg        = (const float*)d_in[7];
    const float* temp      = (const float*)d_in[8];
    float* out             = (float*)d_out;

    __nv_bfloat16 *cls_bf, *q_bf, *Wc_bf, *Wq_bf, *Wg_bf, *cproj, *qproj, *qT, *attn;
    float *iface, *sim;
    cudaGetSymbolAddress((void**)&cls_bf, g_cls_bf);
    cudaGetSymbolAddress((void**)&q_bf,   g_q_bf);
    cudaGetSymbolAddress((void**)&Wc_bf,  g_Wc_bf);
    cudaGetSymbolAddress((void**)&Wq_bf,  g_Wq_bf);
    cudaGetSymbolAddress((void**)&Wg_bf,  g_Wg_bf);
    cudaGetSymbolAddress((void**)&cproj,  g_cproj);
    cudaGetSymbolAddress((void**)&qproj,  g_qproj);
    cudaGetSymbolAddress((void**)&qT,     g_qT);
    cudaGetSymbolAddress((void**)&attn,   g_attn);
    cudaGetSymbolAddress((void**)&iface,  g_iface);
    cudaGetSymbolAddress((void**)&sim,    g_sim);

    cudaFuncSetAttribute(gemm_bf_kernel,
                         cudaFuncAttributeMaxDynamicSharedMemorySize, SM_TOTAL);

    dim3 blk(128);

    // Convert inputs to bf16
    tobf16_kernel<<<2048, 256>>>(classical, cls_bf, (long)MS*DD/4);
    tobf16_kernel<<<2048, 256>>>(quantum,   q_bf,   (long)MS*DD/4);
    tobf16_kernel<<<1024, 256>>>(Wc,        Wc_bf,  (long)DD*DD/4);
    tobf16_kernel<<<1024, 256>>>(Wq,        Wq_bf,  (long)DD*DD/4);
    tobf16_kernel<<<1024, 256>>>(Wg,        Wg_bf,  (long)DD*2*DD/4);

    // 0) qT[b] = bf16(quantum[b]^T)  [D,S]
    transpose_kernel<<<dim3(DD/32, SS/32, BB), 256>>>(quantum, qT);

    // 1) cproj = bf16(classical @ Wc^T + bc)
    gemm_bf_kernel<<<dim3(DD/128, MS/128, 1), blk, SM_TOTAL>>>(
        cls_bf, nullptr, Wc_bf, bc, nullptr, nullptr, cproj,
        DD, DD, DD, DD, 0, 0, 0, 0);

    // 2) qproj = bf16(quantum @ Wq^T + bq)
    gemm_bf_kernel<<<dim3(DD/128, MS/128, 1), blk, SM_TOTAL>>>(
        q_bf, nullptr, Wq_bf, bq, nullptr, nullptr, qproj,
        DD, DD, DD, DD, 0, 0, 0, 0);

    // 3) iface = sigmoid([cproj|qproj] @ Wg^T + bg), K=2048 split at 1024
    gemm_bf_kernel<<<dim3(DD/128, MS/128, 1), blk, SM_TOTAL>>>(
        cproj, qproj, Wg_bf, bg, nullptr, nullptr, iface,
        DD, 2*DD, DD, DD, 0, 0, 0, 1);

    // 4) sim[b] = cproj[b] @ qproj[b]^T  (raw fp32; scale folded into softmax)
    gemm_bf_kernel<<<dim3(SS/128, SS/128, BB), blk, SM_TOTAL>>>(
        cproj, nullptr, qproj, nullptr, nullptr, nullptr, sim,
        SS, DD, DD, DD,
        (long)SS*DD, (long)SS*DD, (long)SS*SS, 2);

    // 5) softmax -> bf16 attn
    softmax_kernel<<<BB*SS, 256>>>(sim, attn, temp);

    // 6) out = classical + iface * (attn[b] @ qT[b]^T)
    gemm_bf_kernel<<<dim3(DD/128, SS/128, BB), blk, SM_TOTAL>>>(
        attn, nullptr, qT, nullptr, classical, iface, out,
        DD, SS, SS, SS,
        (long)SS*SS, (long)DD*SS, (long)SS*DD, 3);
}

// round 7
// speedup vs baseline: 7.1985x; 1.0174x over previous
#include <cuda_runtime.h>
#include <cuda_bf16.h>
#include <math.h>
#include <stdint.h>

// Problem constants
#define BB 4
#define SS 2048
#define DD 1024
#define MS (BB*SS)          // 8192 rows

#define KC  64              // K bf16 elements per chunk (= 128B smem rows)
#define SM_BUF 16384        // one 128x64 bf16 tile
#define NSTAGE 3
#define SM_STAGE (2*SM_BUF)
#define SM_TOTAL (NSTAGE*SM_STAGE)   // 96 KB

// Scratch (no allocations allowed -> device globals)
__device__ __nv_bfloat16 g_cls_bf[MS*DD];            // 16 MB
__device__ __nv_bfloat16 g_q_bf[MS*DD];              // 16 MB
__device__ __nv_bfloat16 g_Wc_bf[DD*DD];             // 2 MB
__device__ __nv_bfloat16 g_Wq_bf[DD*DD];             // 2 MB
__device__ __nv_bfloat16 g_Wg_bf[DD*2*DD];           // 4 MB
__device__ __nv_bfloat16 g_cproj[MS*DD];             // 16 MB
__device__ __nv_bfloat16 g_qproj[MS*DD];             // 16 MB
__device__ __nv_bfloat16 g_qT[(size_t)BB*DD*SS];     // 16 MB
__device__ __nv_bfloat16 g_attn[(size_t)BB*SS*SS];   // 32 MB
__device__ float g_iface[MS*DD];                     // 32 MB
__device__ float g_sim[(size_t)BB*SS*SS];            // 64 MB

// ---------------------------------------------------------------------------
__device__ __forceinline__ uint32_t smem_u32(const void* p) {
    uint32_t a;
    asm("{ .reg .u64 t; cvta.to.shared.u64 t, %1; cvt.u32.u64 %0, t; }" : "=r"(a) : "l"(p));
    return a;
}
__device__ __forceinline__ uint32_t pack_bf16(float lo, float hi) {
    uint32_t u;
    asm("cvt.rn.bf16x2.f32 %0, %1, %2;" : "=r"(u) : "f"(hi), "f"(lo));
    return u;
}

#define CP_COMMIT() asm volatile("cp.async.commit_group;" ::: "memory")
#define CP_WAIT(n)  asm volatile("cp.async.wait_group %0;" :: "n"(n) : "memory")

// Load one 128-row x 64-bf16 chunk, global->smem via cp.async, XOR swizzle.
// 256 threads, 4 x 16B each. Seg s (16B) of row r stored at s ^ (r&7).
__device__ __forceinline__ void load_chunk(const __nv_bfloat16* __restrict__ src, int ld,
                                           int row0, int kc, uint32_t sbuf, int tid) {
    #pragma unroll
    for (int i = 0; i < 4; i++) {
        int idx = i * 256 + tid;
        int row = idx >> 3;
        int seg = idx & 7;
        const __nv_bfloat16* gp = src + (long)(row0 + row) * ld + kc + seg * 8;
        uint32_t off = sbuf + row * 128 + ((seg ^ (row & 7)) << 4);
        asm volatile("cp.async.cg.shared.global [%0], [%1], 16;" :: "r"(off), "l"(gp));
    }
}

#define LDSM4(d, addr) \
    asm volatile("ldmatrix.sync.aligned.m8n8.x4.shared.b16 {%0,%1,%2,%3}, [%4];" \
        : "=r"((d)[0]), "=r"((d)[1]), "=r"((d)[2]), "=r"((d)[3]) : "r"(addr))

__device__ __forceinline__ void mma16(float* c, const uint32_t* a, const uint32_t* b) {
    asm volatile("mma.sync.aligned.m16n8k16.row.col.f32.bf16.bf16.f32 "
                 "{%0,%1,%2,%3}, {%4,%5,%6,%7}, {%8,%9}, {%0,%1,%2,%3};"
                 : "+f"(c[0]), "+f"(c[1]), "+f"(c[2]), "+f"(c[3])
                 : "r"(a[0]), "r"(a[1]), "r"(a[2]), "r"(a[3]), "r"(b[0]), "r"(b[1]));
}

// ---------------------------------------------------------------------------
// NT bf16 tensor-core GEMM: acc[m,n] = sum_k A[m,k] * B[n,k]  (fp32 accum)
// 256 threads, CTA tile 128x128, warp tile 64x32 (2x4 warp grid).
// A-concat: chunk k >= Ksplit reads A2[m, k-Ksplit] (same lda).
// Dual-set: if Ad != null and blockIdx.z == 1, use (Ad,Bd,biasd,Cd) instead.
// mode 0: bf16 store of (acc+bias)   1: fp32 sigmoid(acc+bias)
// mode 2: fp32 raw                   3: fp32 Cls + Ifc*acc
// ---------------------------------------------------------------------------
__global__ __launch_bounds__(256, 2)
void gemm_bf_kernel(const __nv_bfloat16* __restrict__ A,
                    const __nv_bfloat16* __restrict__ A2,
                    const __nv_bfloat16* __restrict__ B,
                    const float* __restrict__ bias,
                    const float* __restrict__ Cls,
                    const float* __restrict__ Ifc,
                    void* __restrict__ Cout,
                    const __nv_bfloat16* __restrict__ Ad,
                    const __nv_bfloat16* __restrict__ Bd,
                    const float* __restrict__ biasd,
                    void* __restrict__ Cd,
                    int N, int K, int Ksplit, int lda,
                    long As_batch, long Bs_batch, long Cs_batch,
                    int mode)
{
    extern __shared__ char smem[];
    uint32_t sb = smem_u32(smem);

    int tid  = threadIdx.x;
    int wid  = tid >> 5;
    int lane = tid & 31;
    int g    = lane >> 2;      // 0..7
    int tig  = lane & 3;       // 0..3
    int mw   = (wid >> 2) * 64;   // 2 row groups
    int nw   = (wid & 3) * 32;    // 4 col groups

    int bz = blockIdx.z;
    if (Ad && bz == 1) {       // dual projection mode
        A = Ad; B = Bd; bias = biasd; Cout = Cd;
        bz = 0;
    }
    A += bz * As_batch;
    if (A2) A2 += bz * As_batch;
    B += bz * Bs_batch;
    if (Cls) Cls += bz * Cs_batch;
    if (Ifc) Ifc += bz * Cs_batch;

    int row0 = blockIdx.y * 128;
    int col0 = blockIdx.x * 128;

    // ldmatrix addressing: lane t serves matrix q=t>>3, row r=t&7.
    int r  = lane & 7;
    int q  = lane >> 3;
    int ql = q & 1;
    int qh = q >> 1;
    uint32_t segoff[4];
    #pragma unroll
    for (int ks = 0; ks < 4; ks++)
        segoff[ks] = (uint32_t)((((2 * ks + qh) ^ r) << 4));
    uint32_t Arow = (uint32_t)((mw + ql * 8 + r) * 128);
    uint32_t Brow = (uint32_t)((nw + ql * 8 + r) * 128);

    float acc[4][4][4];
    #pragma unroll
    for (int i = 0; i < 4; i++)
        #pragma unroll
        for (int j = 0; j < 4; j++)
            #pragma unroll
            for (int p = 0; p < 4; p++) acc[i][j][p] = 0.0f;

    const int NC = K / KC;

    // prologue: chunks 0,1 -> stages 0,1
    #pragma unroll
    for (int p = 0; p < 2; p++) {
        int kt = p * KC;
        const __nv_bfloat16* Ap; int kA;
        if (kt < Ksplit) { Ap = A;  kA = kt; }
        else             { Ap = A2; kA = kt - Ksplit; }
        uint32_t stg = sb + p * SM_STAGE;
        load_chunk(Ap, lda, row0, kA, stg, tid);
        load_chunk(B,  K,   col0, kt, stg + SM_BUF, tid);
        CP_COMMIT();
    }

    int stage = 0;
    for (int ch = 0; ch < NC; ch++) {
        if (ch + 2 < NC) {
            int kt = (ch + 2) * KC;
            const __nv_bfloat16* Ap; int kA;
            if (kt < Ksplit) { Ap = A;  kA = kt; }
            else             { Ap = A2; kA = kt - Ksplit; }
            int ns = stage + 2; if (ns >= NSTAGE) ns -= NSTAGE;
            uint32_t stg = sb + ns * SM_STAGE;
            load_chunk(Ap, lda, row0, kA, stg, tid);
            load_chunk(B,  K,   col0, kt, stg + SM_BUF, tid);
            CP_COMMIT();
            CP_WAIT(2);
        } else if (ch + 1 < NC) {
            CP_WAIT(1);
        } else {
            CP_WAIT(0);
        }
        __syncthreads();

        uint32_t At = sb + stage * SM_STAGE + Arow;
        uint32_t Bt = sb + stage * SM_STAGE + SM_BUF + Brow;

        #pragma unroll
        for (int ks = 0; ks < 4; ks++) {          // 4 x k16 = 64
            uint32_t so = segoff[ks];
            uint32_t af[4][4];
            #pragma unroll
            for (int i = 0; i < 4; i++)
                LDSM4(af[i], At + i * 2048 + so);
            uint32_t bf[4][2];
            #pragma unroll
            for (int j2 = 0; j2 < 2; j2++) {
                uint32_t t[4];
                LDSM4(t, Bt + j2 * 2048 + so);
                bf[2 * j2][0]     = t[0];
                bf[2 * j2 + 1][0] = t[1];
                bf[2 * j2][1]     = t[2];
                bf[2 * j2 + 1][1] = t[3];
            }
            #pragma unroll
            for (int i = 0; i < 4; i++)
                #pragma unroll
                for (int j = 0; j < 4; j++)
                    mma16(acc[i][j], af[i], bf[j]);
        }
        __syncthreads();

        stage++; if (stage >= NSTAGE) stage = 0;
    }

    // Epilogue: c0,c1 at (row g, cols 2tig..), c2,c3 at row g+8
    #pragma unroll
    for (int i = 0; i < 4; i++) {
        int rA = row0 + mw + 16 * i + g;
        int rB = rA + 8;
        #pragma unroll
        for (int j = 0; j < 4; j++) {
            int c = col0 + nw + 8 * j + 2 * tig;
            float2 v0 = make_float2(acc[i][j][0], acc[i][j][1]);
            float2 v1 = make_float2(acc[i][j][2], acc[i][j][3]);

            if (mode == 0) {
                float2 bb = *reinterpret_cast<const float2*>(bias + c);
                __nv_bfloat16* Cb = (__nv_bfloat16*)Cout + bz * Cs_batch;
                *reinterpret_cast<uint32_t*>(Cb + (long)rA * N + c) =
                    pack_bf16(v0.x + bb.x, v0.y + bb.y);
                *reinterpret_cast<uint32_t*>(Cb + (long)rB * N + c) =
                    pack_bf16(v1.x + bb.x, v1.y + bb.y);
            } else {
                float* Cf = (float*)Cout + bz * Cs_batch;
                if (mode == 1) {
                    float2 bb = *reinterpret_cast<const float2*>(bias + c);
                    v0.x = 1.0f / (1.0f + expf(-(v0.x + bb.x)));
                    v0.y = 1.0f / (1.0f + expf(-(v0.y + bb.y)));
                    v1.x = 1.0f / (1.0f + expf(-(v1.x + bb.x)));
                    v1.y = 1.0f / (1.0f + expf(-(v1.y + bb.y)));
                } else if (mode == 3) {
                    long i0 = (long)rA * N + c;
                    long i1 = (long)rB * N + c;
                    float2 cl0 = *reinterpret_cast<const float2*>(Cls + i0);
                    float2 cl1 = *reinterpret_cast<const float2*>(Cls + i1);
                    float2 fi0 = *reinterpret_cast<const float2*>(Ifc + i0);
                    float2 fi1 = *reinterpret_cast<const float2*>(Ifc + i1);
                    v0.x = cl0.x + fi0.x * v0.x;  v0.y = cl0.y + fi0.y * v0.y;
                    v1.x = cl1.x + fi1.x * v1.x;  v1.y = cl1.y + fi1.y * v1.y;
                }
                *reinterpret_cast<float2*>(Cf + (long)rA * N + c) = v0;
                *reinterpret_cast<float2*>(Cf + (long)rB * N + c) = v1;
            }
        }
    }
}

// ---------------------------------------------------------------------------
// Fused fp32 -> bf16 conversion of all five inputs (float4 grid-stride).
// Segments: cls (2M f4), q (2M), Wc (256K), Wq (256K), Wg (512K).
// ---------------------------------------------------------------------------
#define N4_CLS ((long)MS*DD/4)
#define N4_W   ((long)DD*DD/4)
#define N4_WG  ((long)DD*2*DD/4)
__global__ __launch_bounds__(256)
void tobf16_all_kernel(const float* __restrict__ cls, const float* __restrict__ q,
                       const float* __restrict__ Wc, const float* __restrict__ Wq,
                       const float* __restrict__ Wg,
                       __nv_bfloat16* __restrict__ cls_o, __nv_bfloat16* __restrict__ q_o,
                       __nv_bfloat16* __restrict__ Wc_o, __nv_bfloat16* __restrict__ Wq_o,
                       __nv_bfloat16* __restrict__ Wg_o)
{
    const long total = 2 * N4_CLS + 2 * N4_W + N4_WG;
    long i = (long)blockIdx.x * blockDim.x + threadIdx.x;
    long stride = (long)gridDim.x * blockDim.x;
    for (; i < total; i += stride) {
        const float* src; __nv_bfloat16* dst; long off;
        if (i < N4_CLS)                        { src = cls; dst = cls_o; off = i; }
        else if (i < 2 * N4_CLS)               { src = q;   dst = q_o;   off = i - N4_CLS; }
        else if (i < 2 * N4_CLS + N4_W)        { src = Wc;  dst = Wc_o;  off = i - 2 * N4_CLS; }
        else if (i < 2 * N4_CLS + 2 * N4_W)    { src = Wq;  dst = Wq_o;  off = i - 2 * N4_CLS - N4_W; }
        else                                   { src = Wg;  dst = Wg_o;  off = i - 2 * N4_CLS - 2 * N4_W; }
        float4 v = reinterpret_cast<const float4*>(src)[off];
        uint2 o;
        o.x = pack_bf16(v.x, v.y);
        o.y = pack_bf16(v.z, v.w);
        reinterpret_cast<uint2*>(dst)[off] = o;
    }
}

// ---------------------------------------------------------------------------
// Transpose per batch: fp32 in [S,D] -> bf16 out [D,S]
// ---------------------------------------------------------------------------
__global__ __launch_bounds__(256)
void transpose_kernel(const float* __restrict__ in, __nv_bfloat16* __restrict__ out)
{
    __shared__ float t[32][33];
    int bz = blockIdx.z;
    in  += (long)bz * SS * DD;
    out += (long)bz * DD * SS;

    int d0 = blockIdx.x * 32;
    int s0 = blockIdx.y * 32;
    int tx = threadIdx.x & 31;
    int ty = threadIdx.x >> 5;   // 0..7

    #pragma unroll
    for (int i = 0; i < 4; i++) {
        int s = s0 + ty + i * 8;
        t[ty + i * 8][tx] = in[(long)s * DD + d0 + tx];
    }
    __syncthreads();
    #pragma unroll
    for (int i = 0; i < 4; i++) {
        int d = d0 + ty + i * 8;
        out[(long)d * SS + s0 + tx] = __float2bfloat16(t[tx][ty + i * 8]);
    }
}

// ---------------------------------------------------------------------------
// Row softmax over S=2048, scale (1/sqrt(D))/T; fp32 in, bf16 out. float4 I/O.
// ---------------------------------------------------------------------------
__global__ __launch_bounds__(256)
void softmax_kernel(const float* __restrict__ sim, __nv_bfloat16* __restrict__ attn,
                    const float* __restrict__ temp)
{
    __shared__ float red_max[8];
    __shared__ float red_sum[8];

    long row = blockIdx.x;
    const float4* p4 = reinterpret_cast<const float4*>(sim + row * (long)SS);
    __nv_bfloat16* po = attn + row * (long)SS;
    int tid  = threadIdx.x;
    int lane = tid & 31;
    int wid  = tid >> 5;

    float s = (1.0f / 32.0f) / (*temp);

    float4 a = p4[tid];
    float4 b = p4[tid + 256];
    float v[8] = {a.x * s, a.y * s, a.z * s, a.w * s,
                  b.x * s, b.y * s, b.z * s, b.w * s};
    float mx = v[0];
    #pragma unroll
    for (int i = 1; i < 8; i++) mx = fmaxf(mx, v[i]);
    #pragma unroll
    for (int o = 16; o > 0; o >>= 1)
        mx = fmaxf(mx, __shfl_xor_sync(0xffffffffu, mx, o));
    if (lane == 0) red_max[wid] = mx;
    __syncthreads();
    mx = red_max[0];
    #pragma unroll
    for (int w = 1; w < 8; w++) mx = fmaxf(mx, red_max[w]);

    float sum = 0.0f;
    #pragma unroll
    for (int i = 0; i < 8; i++) {
        v[i] = expf(v[i] - mx);
        sum += v[i];
    }
    #pragma unroll
    for (int o = 16; o > 0; o >>= 1)
        sum += __shfl_xor_sync(0xffffffffu, sum, o);
    if (lane == 0) red_sum[wid] = sum;
    __syncthreads();
    sum = 0.0f;
    #pragma unroll
    for (int w = 0; w < 8; w++) sum += red_sum[w];

    float inv = 1.0f / sum;
    uint2 o0, o1;
    o0.x = pack_bf16(v[0] * inv, v[1] * inv);
    o0.y = pack_bf16(v[2] * inv, v[3] * inv);
    o1.x = pack_bf16(v[4] * inv, v[5] * inv);
    o1.y = pack_bf16(v[6] * inv, v[7] * inv);
    reinterpret_cast<uint2*>(po)[tid] = o0;
    reinterpret_cast<uint2*>(po)[tid + 256] = o1;
}

// ---------------------------------------------------------------------------
extern "C" void kernel_launch(void* const* d_in, const int* in_sizes, int n_in,
                              void* d_out, int out_size)
{
    const float* classical = (const float*)d_in[0];
    const float* quantum   = (const float*)d_in[1];
    const float* Wc        = (const float*)d_in[2];
    const float* bc        = (const float*)d_in[3];
    const float* Wq        = (const float*)d_in[4];
    const float* bq        = (const float*)d_in[5];
    const float* Wg        = (const float*)d_in[6];
    const float* bg        = (const float*)d_in[7];
    const float* temp      = (const float*)d_in[8];
    float* out             = (float*)d_out;

    __nv_bfloat16 *cls_bf, *q_bf, *Wc_bf, *Wq_bf, *Wg_bf, *cproj, *qproj, *qT, *attn;
    float *iface, *sim;
    cudaGetSymbolAddress((void**)&cls_bf, g_cls_bf);
    cudaGetSymbolAddress((void**)&q_bf,   g_q_bf);
    cudaGetSymbolAddress((void**)&Wc_bf,  g_Wc_bf);
    cudaGetSymbolAddress((void**)&Wq_bf,  g_Wq_bf);
    cudaGetSymbolAddress((void**)&Wg_bf,  g_Wg_bf);
    cudaGetSymbolAddress((void**)&cproj,  g_cproj);
    cudaGetSymbolAddress((void**)&qproj,  g_qproj);
    cudaGetSymbolAddress((void**)&qT,     g_qT);
    cudaGetSymbolAddress((void**)&attn,   g_attn);
    cudaGetSymbolAddress((void**)&iface,  g_iface);
    cudaGetSymbolAddress((void**)&sim,    g_sim);

    cudaFuncSetAttribute(gemm_bf_kernel,
                         cudaFuncAttributeMaxDynamicSharedMemorySize, SM_TOTAL);

    dim3 blk(256);

    // Convert all inputs to bf16 (single launch)
    tobf16_all_kernel<<<2048, 256>>>(classical, quantum, Wc, Wq, Wg,
                                     cls_bf, q_bf, Wc_bf, Wq_bf, Wg_bf);

    // 0) qT[b] = bf16(quantum[b]^T)  [D,S]
    transpose_kernel<<<dim3(DD/32, SS/32, BB), 256>>>(quantum, qT);

    // 1+2) fused dual projection:
    //   z=0: cproj = bf16(classical @ Wc^T + bc)
    //   z=1: qproj = bf16(quantum   @ Wq^T + bq)
    gemm_bf_kernel<<<dim3(DD/128, MS/128, 2), blk, SM_TOTAL>>>(
        cls_bf, nullptr, Wc_bf, bc, nullptr, nullptr, cproj,
        q_bf, Wq_bf, bq, qproj,
        DD, DD, DD, DD, 0, 0, 0, 0);

    // 3) iface = sigmoid([cproj|qproj] @ Wg^T + bg), K=2048 split at 1024
    gemm_bf_kernel<<<dim3(DD/128, MS/128, 1), blk, SM_TOTAL>>>(
        cproj, qproj, Wg_bf, bg, nullptr, nullptr, iface,
        nullptr, nullptr, nullptr, nullptr,
        DD, 2*DD, DD, DD, 0, 0, 0, 1);

    // 4) sim[b] = cproj[b] @ qproj[b]^T  (raw fp32; scale folded into softmax)
    gemm_bf_kernel<<<dim3(SS/128, SS/128, BB), blk, SM_TOTAL>>>(
        cproj, nullptr, qproj, nullptr, nullptr, nullptr, sim,
        nullptr, nullptr, nullptr, nullptr,
        SS, DD, DD, DD,
        (long)SS*DD, (long)SS*DD, (long)SS*SS, 2);

    // 5) softmax -> bf16 attn
    softmax_kernel<<<BB*SS, 256>>>(sim, attn, temp);

    // 6) out = classical + iface * (attn[b] @ qT[b]^T)
    gemm_bf_kernel<<<dim3(DD/128, SS/128, BB), blk, SM_TOTAL>>>(
        attn, nullptr, qT, nullptr, classical, iface, out,
        nullptr, nullptr, nullptr, nullptr,
        DD, SS, SS, SS,
        (long)SS*SS, (long)DD*SS, (long)SS*DD, 3);
}

// round 8
// speedup vs baseline: 7.5984x; 1.0556x over previous
#include <cuda_runtime.h>
#include <cuda_bf16.h>
#include <math.h>
#include <stdint.h>

// Problem constants
#define BB 4
#define SS 2048
#define DD 1024
#define MS (BB*SS)          // 8192 rows

#define KC  64              // K bf16 elements per chunk (= 128B smem rows)
#define SM_BUF 16384        // one 128x64 bf16 tile
#define NSTAGE 3
#define SM_STAGE (2*SM_BUF)
#define SM_TOTAL (NSTAGE*SM_STAGE)   // 96 KB

// Scratch (no allocations allowed -> device globals)
__device__ __nv_bfloat16 g_cls_bf[MS*DD];            // 16 MB
__device__ __nv_bfloat16 g_q_bf[MS*DD];              // 16 MB
__device__ __nv_bfloat16 g_Wc_bf[DD*DD];             // 2 MB
__device__ __nv_bfloat16 g_Wq_bf[DD*DD];             // 2 MB
__device__ __nv_bfloat16 g_Wg_bf[DD*2*DD];           // 4 MB
__device__ __nv_bfloat16 g_cproj[MS*DD];             // 16 MB
__device__ __nv_bfloat16 g_qproj[MS*DD];             // 16 MB
__device__ __nv_bfloat16 g_qT[(size_t)BB*DD*SS];     // 16 MB
__device__ __nv_bfloat16 g_attn[(size_t)BB*SS*SS];   // 32 MB
__device__ float g_iface[MS*DD];                     // 32 MB
__device__ float g_sim[(size_t)BB*SS*SS];            // 64 MB

// ---------------------------------------------------------------------------
__device__ __forceinline__ uint32_t smem_u32(const void* p) {
    uint32_t a;
    asm("{ .reg .u64 t; cvta.to.shared.u64 t, %1; cvt.u32.u64 %0, t; }" : "=r"(a) : "l"(p));
    return a;
}
__device__ __forceinline__ uint32_t pack_bf16(float lo, float hi) {
    uint32_t u;
    asm("cvt.rn.bf16x2.f32 %0, %1, %2;" : "=r"(u) : "f"(hi), "f"(lo));
    return u;
}

#define CP_COMMIT() asm volatile("cp.async.commit_group;" ::: "memory")
#define CP_WAIT(n)  asm volatile("cp.async.wait_group %0;" :: "n"(n) : "memory")

#define LDSM4(d, addr) \
    asm volatile("ldmatrix.sync.aligned.m8n8.x4.shared.b16 {%0,%1,%2,%3}, [%4];" \
        : "=r"((d)[0]), "=r"((d)[1]), "=r"((d)[2]), "=r"((d)[3]) : "r"(addr))

__device__ __forceinline__ void mma16(float* c, const uint32_t* a, const uint32_t* b) {
    asm volatile("mma.sync.aligned.m16n8k16.row.col.f32.bf16.bf16.f32 "
                 "{%0,%1,%2,%3}, {%4,%5,%6,%7}, {%8,%9}, {%0,%1,%2,%3};"
                 : "+f"(c[0]), "+f"(c[1]), "+f"(c[2]), "+f"(c[3])
                 : "r"(a[0]), "r"(a[1]), "r"(a[2]), "r"(a[3]), "r"(b[0]), "r"(b[1]));
}

// Issue one chunk's A+B loads (8 cp.async per thread), single commit.
__device__ __forceinline__ void issue_chunk(const __nv_bfloat16* __restrict__ baseA,
                                            const __nv_bfloat16* __restrict__ baseB,
                                            const int* rowoffA, const int* rowoffB,
                                            const uint32_t* smoff, uint32_t stg) {
    #pragma unroll
    for (int i = 0; i < 4; i++)
        asm volatile("cp.async.cg.shared.global [%0], [%1], 16;"
            :: "r"(stg + smoff[i]), "l"(baseA + rowoffA[i]));
    #pragma unroll
    for (int i = 0; i < 4; i++)
        asm volatile("cp.async.cg.shared.global [%0], [%1], 16;"
            :: "r"(stg + SM_BUF + smoff[i]), "l"(baseB + rowoffB[i]));
    CP_COMMIT();
}

// ---------------------------------------------------------------------------
// NT bf16 tensor-core GEMM: acc[m,n] = sum_k A[m,k] * B[n,k]  (fp32 accum)
// 256 threads, CTA tile 128x128, warp tile 64x32 (2x4 warp grid).
// A-concat: chunk k >= Ksplit reads A2[m, k-Ksplit] (same lda).
// Dual-set: if Ad != null and blockIdx.z == 1, use (Ad,Bd,biasd,Cd) instead.
// mode 0: bf16 store of (acc+bias)   1: fp32 sigmoid(acc+bias)
// mode 2: fp32 raw                   3: fp32 Cls + Ifc*acc
// ---------------------------------------------------------------------------
__global__ __launch_bounds__(256, 2)
void gemm_bf_kernel(const __nv_bfloat16* __restrict__ A,
                    const __nv_bfloat16* __restrict__ A2,
                    const __nv_bfloat16* __restrict__ B,
                    const float* __restrict__ bias,
                    const float* __restrict__ Cls,
                    const float* __restrict__ Ifc,
                    void* __restrict__ Cout,
                    const __nv_bfloat16* __restrict__ Ad,
                    const __nv_bfloat16* __restrict__ Bd,
                    const float* __restrict__ biasd,
                    void* __restrict__ Cd,
                    int N, int K, int Ksplit, int lda,
                    long As_batch, long Bs_batch, long Cs_batch,
                    int mode)
{
    extern __shared__ char smem[];
    uint32_t sb = smem_u32(smem);

    int tid  = threadIdx.x;
    int wid  = tid >> 5;
    int lane = tid & 31;
    int g    = lane >> 2;      // 0..7
    int tig  = lane & 3;       // 0..3
    int mw   = (wid >> 2) * 64;   // 2 row groups
    int nw   = (wid & 3) * 32;    // 4 col groups

    int bz = blockIdx.z;
    if (Ad && bz == 1) {       // dual projection mode
        A = Ad; B = Bd; bias = biasd; Cout = Cd;
        bz = 0;
    }
    A += bz * As_batch;
    if (A2) A2 += bz * As_batch;
    B += bz * Bs_batch;
    if (Cls) Cls += bz * Cs_batch;
    if (Ifc) Ifc += bz * Cs_batch;

    int row0 = blockIdx.y * 128;
    int col0 = blockIdx.x * 128;

    // Hoisted per-thread load offsets: thread handles 4 rows for A and B.
    int rowoffA[4], rowoffB[4];
    uint32_t smoff[4];
    #pragma unroll
    for (int i = 0; i < 4; i++) {
        int idx = i * 256 + tid;
        int row = idx >> 3;
        int seg = idx & 7;
        rowoffA[i] = (row0 + row) * lda + seg * 8;
        rowoffB[i] = (col0 + row) * K + seg * 8;
        smoff[i]   = (uint32_t)(row * 128 + ((seg ^ (row & 7)) << 4));
    }

    // ldmatrix addressing: lane t serves matrix q=t>>3, row r=t&7.
    int r  = lane & 7;
    int q  = lane >> 3;
    int ql = q & 1;
    int qh = q >> 1;
    uint32_t segoff[4];
    #pragma unroll
    for (int ks = 0; ks < 4; ks++)
        segoff[ks] = (uint32_t)((((2 * ks + qh) ^ r) << 4));
    uint32_t ArowB = sb + (uint32_t)((mw + ql * 8 + r) * 128);
    uint32_t BrowB = sb + SM_BUF + (uint32_t)((nw + ql * 8 + r) * 128);

    float acc[4][4][4];
    #pragma unroll
    for (int i = 0; i < 4; i++)
        #pragma unroll
        for (int j = 0; j < 4; j++)
            #pragma unroll
            for (int p = 0; p < 4; p++) acc[i][j][p] = 0.0f;

    const int NC = K / KC;

    // prologue: chunks 0,1 -> stages 0,1
    #pragma unroll
    for (int p = 0; p < 2; p++) {
        int kt = p * KC;
        const __nv_bfloat16* bA = (kt < Ksplit) ? (A + kt) : (A2 + (kt - Ksplit));
        issue_chunk(bA, B + kt, rowoffA, rowoffB, smoff, sb + p * SM_STAGE);
    }

    int stage = 0;
    for (int ch = 0; ch < NC; ch++) {
        if (ch + 1 < NC) { CP_WAIT(1); } else { CP_WAIT(0); }
        __syncthreads();

        uint32_t At = ArowB + stage * SM_STAGE;
        uint32_t Bt = BrowB + stage * SM_STAGE;

        #pragma unroll
        for (int ks = 0; ks < 4; ks++) {          // 4 x k16 = 64
            uint32_t so = segoff[ks];
            uint32_t af[4][4];
            #pragma unroll
            for (int i = 0; i < 4; i++)
                LDSM4(af[i], At + i * 2048 + so);
            uint32_t bf[4][2];
            #pragma unroll
            for (int j2 = 0; j2 < 2; j2++) {
                uint32_t t[4];
                LDSM4(t, Bt + j2 * 2048 + so);
                bf[2 * j2][0]     = t[0];
                bf[2 * j2 + 1][0] = t[1];
                bf[2 * j2][1]     = t[2];
                bf[2 * j2 + 1][1] = t[3];
            }
            #pragma unroll
            for (int i = 0; i < 4; i++)
                #pragma unroll
                for (int j = 0; j < 4; j++)
                    mma16(acc[i][j], af[i], bf[j]);
        }

        if (ch + 2 < NC) {
            int kt = (ch + 2) * KC;
            const __nv_bfloat16* bA = (kt < Ksplit) ? (A + kt) : (A2 + (kt - Ksplit));
            int ns = stage + 2; if (ns >= NSTAGE) ns -= NSTAGE;
            issue_chunk(bA, B + kt, rowoffA, rowoffB, smoff, sb + ns * SM_STAGE);
        }
        stage++; if (stage >= NSTAGE) stage = 0;
    }

    // Epilogue: c0,c1 at (row g, cols 2tig..), c2,c3 at row g+8
    #pragma unroll
    for (int i = 0; i < 4; i++) {
        int rA = row0 + mw + 16 * i + g;
        int rB = rA + 8;
        #pragma unroll
        for (int j = 0; j < 4; j++) {
            int c = col0 + nw + 8 * j + 2 * tig;
            float2 v0 = make_float2(acc[i][j][0], acc[i][j][1]);
            float2 v1 = make_float2(acc[i][j][2], acc[i][j][3]);

            if (mode == 0) {
                float2 bb = *reinterpret_cast<const float2*>(bias + c);
                __nv_bfloat16* Cb = (__nv_bfloat16*)Cout + bz * Cs_batch;
                *reinterpret_cast<uint32_t*>(Cb + (long)rA * N + c) =
                    pack_bf16(v0.x + bb.x, v0.y + bb.y);
                *reinterpret_cast<uint32_t*>(Cb + (long)rB * N + c) =
                    pack_bf16(v1.x + bb.x, v1.y + bb.y);
            } else {
                float* Cf = (float*)Cout + bz * Cs_batch;
                if (mode == 1) {
                    float2 bb = *reinterpret_cast<const float2*>(bias + c);
                    v0.x = 1.0f / (1.0f + __expf(-(v0.x + bb.x)));
                    v0.y = 1.0f / (1.0f + __expf(-(v0.y + bb.y)));
                    v1.x = 1.0f / (1.0f + __expf(-(v1.x + bb.x)));
                    v1.y = 1.0f / (1.0f + __expf(-(v1.y + bb.y)));
                } else if (mode == 3) {
                    long i0 = (long)rA * N + c;
                    long i1 = (long)rB * N + c;
                    float2 cl0 = *reinterpret_cast<const float2*>(Cls + i0);
                    float2 cl1 = *reinterpret_cast<const float2*>(Cls + i1);
                    float2 fi0 = *reinterpret_cast<const float2*>(Ifc + i0);
                    float2 fi1 = *reinterpret_cast<const float2*>(Ifc + i1);
                    v0.x = cl0.x + fi0.x * v0.x;  v0.y = cl0.y + fi0.y * v0.y;
                    v1.x = cl1.x + fi1.x * v1.x;  v1.y = cl1.y + fi1.y * v1.y;
                }
                *reinterpret_cast<float2*>(Cf + (long)rA * N + c) = v0;
                *reinterpret_cast<float2*>(Cf + (long)rB * N + c) = v1;
            }
        }
    }
}

// ---------------------------------------------------------------------------
// Fused fp32 -> bf16 conversion of all five inputs (float4 grid-stride).
// ---------------------------------------------------------------------------
#define N4_CLS ((long)MS*DD/4)
#define N4_W   ((long)DD*DD/4)
#define N4_WG  ((long)DD*2*DD/4)
__global__ __launch_bounds__(256)
void tobf16_all_kernel(const float* __restrict__ cls, const float* __restrict__ q,
                       const float* __restrict__ Wc, const float* __restrict__ Wq,
                       const float* __restrict__ Wg,
                       __nv_bfloat16* __restrict__ cls_o, __nv_bfloat16* __restrict__ q_o,
                       __nv_bfloat16* __restrict__ Wc_o, __nv_bfloat16* __restrict__ Wq_o,
                       __nv_bfloat16* __restrict__ Wg_o)
{
    const long total = 2 * N4_CLS + 2 * N4_W + N4_WG;
    long i = (long)blockIdx.x * blockDim.x + threadIdx.x;
    long stride = (long)gridDim.x * blockDim.x;
    for (; i < total; i += stride) {
        const float* src; __nv_bfloat16* dst; long off;
        if (i < N4_CLS)                        { src = cls; dst = cls_o; off = i; }
        else if (i < 2 * N4_CLS)               { src = q;   dst = q_o;   off = i - N4_CLS; }
        else if (i < 2 * N4_CLS + N4_W)        { src = Wc;  dst = Wc_o;  off = i - 2 * N4_CLS; }
        else if (i < 2 * N4_CLS + 2 * N4_W)    { src = Wq;  dst = Wq_o;  off = i - 2 * N4_CLS - N4_W; }
        else                                   { src = Wg;  dst = Wg_o;  off = i - 2 * N4_CLS - 2 * N4_W; }
        float4 v = reinterpret_cast<const float4*>(src)[off];
        uint2 o;
        o.x = pack_bf16(v.x, v.y);
        o.y = pack_bf16(v.z, v.w);
        reinterpret_cast<uint2*>(dst)[off] = o;
    }
}

// ---------------------------------------------------------------------------
// Transpose per batch: fp32 in [S,D] -> bf16 out [D,S]
// ---------------------------------------------------------------------------
__global__ __launch_bounds__(256)
void transpose_kernel(const float* __restrict__ in, __nv_bfloat16* __restrict__ out)
{
    __shared__ float t[32][33];
    int bz = blockIdx.z;
    in  += (long)bz * SS * DD;
    out += (long)bz * DD * SS;

    int d0 = blockIdx.x * 32;
    int s0 = blockIdx.y * 32;
    int tx = threadIdx.x & 31;
    int ty = threadIdx.x >> 5;   // 0..7

    #pragma unroll
    for (int i = 0; i < 4; i++) {
        int s = s0 + ty + i * 8;
        t[ty + i * 8][tx] = in[(long)s * DD + d0 + tx];
    }
    __syncthreads();
    #pragma unroll
    for (int i = 0; i < 4; i++) {
        int d = d0 + ty + i * 8;
        out[(long)d * SS + s0 + tx] = __float2bfloat16(t[tx][ty + i * 8]);
    }
}

// ---------------------------------------------------------------------------
// Row softmax over S=2048, scale (1/sqrt(D))/T; fp32 in, bf16 out. float4 I/O.
// ---------------------------------------------------------------------------
__global__ __launch_bounds__(256)
void softmax_kernel(const float* __restrict__ sim, __nv_bfloat16* __restrict__ attn,
                    const float* __restrict__ temp)
{
    __shared__ float red_max[8];
    __shared__ float red_sum[8];

    long row = blockIdx.x;
    const float4* p4 = reinterpret_cast<const float4*>(sim + row * (long)SS);
    __nv_bfloat16* po = attn + row * (long)SS;
    int tid  = threadIdx.x;
    int lane = tid & 31;
    int wid  = tid >> 5;

    float s = (1.0f / 32.0f) / (*temp);

    float4 a = p4[tid];
    float4 b = p4[tid + 256];
    float v[8] = {a.x * s, a.y * s, a.z * s, a.w * s,
                  b.x * s, b.y * s, b.z * s, b.w * s};
    float mx = v[0];
    #pragma unroll
    for (int i = 1; i < 8; i++) mx = fmaxf(mx, v[i]);
    #pragma unroll
    for (int o = 16; o > 0; o >>= 1)
        mx = fmaxf(mx, __shfl_xor_sync(0xffffffffu, mx, o));
    if (lane == 0) red_max[wid] = mx;
    __syncthreads();
    mx = red_max[0];
    #pragma unroll
    for (int w = 1; w < 8; w++) mx = fmaxf(mx, red_max[w]);

    float sum = 0.0f;
    #pragma unroll
    for (int i = 0; i < 8; i++) {
        v[i] = __expf(v[i] - mx);
        sum += v[i];
    }
    #pragma unroll
    for (int o = 16; o > 0; o >>= 1)
        sum += __shfl_xor_sync(0xffffffffu, sum, o);
    if (lane == 0) red_sum[wid] = sum;
    __syncthreads();
    sum = 0.0f;
    #pragma unroll
    for (int w = 0; w < 8; w++) sum += red_sum[w];

    float inv = 1.0f / sum;
    uint2 o0, o1;
    o0.x = pack_bf16(v[0] * inv, v[1] * inv);
    o0.y = pack_bf16(v[2] * inv, v[3] * inv);
    o1.x = pack_bf16(v[4] * inv, v[5] * inv);
    o1.y = pack_bf16(v[6] * inv, v[7] * inv);
    reinterpret_cast<uint2*>(po)[tid] = o0;
    reinterpret_cast<uint2*>(po)[tid + 256] = o1;
}

// ---------------------------------------------------------------------------
extern "C" void kernel_launch(void* const* d_in, const int* in_sizes, int n_in,
                              void* d_out, int out_size)
{
    const float* classical = (const float*)d_in[0];
    const float* quantum   = (const float*)d_in[1];
    const float* Wc        = (const float*)d_in[2];
    const float* bc        = (const float*)d_in[3];
    const float* Wq        = (const float*)d_in[4];
    const float* bq        = (const float*)d_in[5];
    const float* Wg        = (const float*)d_in[6];
    const float* bg        = (const float*)d_in[7];
    const float* temp      = (const float*)d_in[8];
    float* out             = (float*)d_out;

    __nv_bfloat16 *cls_bf, *q_bf, *Wc_bf, *Wq_bf, *Wg_bf, *cproj, *qproj, *qT, *attn;
    float *iface, *sim;
    cudaGetSymbolAddress((void**)&cls_bf, g_cls_bf);
    cudaGetSymbolAddress((void**)&q_bf,   g_q_bf);
    cudaGetSymbolAddress((void**)&Wc_bf,  g_Wc_bf);
    cudaGetSymbolAddress((void**)&Wq_bf,  g_Wq_bf);
    cudaGetSymbolAddress((void**)&Wg_bf,  g_Wg_bf);
    cudaGetSymbolAddress((void**)&cproj,  g_cproj);
    cudaGetSymbolAddress((void**)&qproj,  g_qproj);
    cudaGetSymbolAddress((void**)&qT,     g_qT);
    cudaGetSymbolAddress((void**)&attn,   g_attn);
    cudaGetSymbolAddress((void**)&iface,  g_iface);
    cudaGetSymbolAddress((void**)&sim,    g_sim);

    cudaFuncSetAttribute(gemm_bf_kernel,
                         cudaFuncAttributeMaxDynamicSharedMemorySize, SM_TOTAL);

    dim3 blk(256);

    // Convert all inputs to bf16 (single launch)
    tobf16_all_kernel<<<2048, 256>>>(classical, quantum, Wc, Wq, Wg,
                                     cls_bf, q_bf, Wc_bf, Wq_bf, Wg_bf);

    // 0) qT[b] = bf16(quantum[b]^T)  [D,S]
    transpose_kernel<<<dim3(DD/32, SS/32, BB), 256>>>(quantum, qT);

    // 1+2) fused dual projection:
    //   z=0: cproj = bf16(classical @ Wc^T + bc)
    //   z=1: qproj = bf16(quantum   @ Wq^T + bq)
    gemm_bf_kernel<<<dim3(DD/128, MS/128, 2), blk, SM_TOTAL>>>(
        cls_bf, nullptr, Wc_bf, bc, nullptr, nullptr, cproj,
        q_bf, Wq_bf, bq, qproj,
        DD, DD, DD, DD, 0, 0, 0, 0);

    // 3) iface = sigmoid([cproj|qproj] @ Wg^T + bg), K=2048 split at 1024
    gemm_bf_kernel<<<dim3(DD/128, MS/128, 1), blk, SM_TOTAL>>>(
        cproj, qproj, Wg_bf, bg, nullptr, nullptr, iface,
        nullptr, nullptr, nullptr, nullptr,
        DD, 2*DD, DD, DD, 0, 0, 0, 1);

    // 4) sim[b] = cproj[b] @ qproj[b]^T  (raw fp32; scale folded into softmax)
    gemm_bf_kernel<<<dim3(SS/128, SS/128, BB), blk, SM_TOTAL>>>(
        cproj, nullptr, qproj, nullptr, nullptr, nullptr, sim,
        nullptr, nullptr, nullptr, nullptr,
        SS, DD, DD, DD,
        (long)SS*DD, (long)SS*DD, (long)SS*SS, 2);

    // 5) softmax -> bf16 attn
    softmax_kernel<<<BB*SS, 256>>>(sim, attn, temp);

    // 6) out = classical + iface * (attn[b] @ qT[b]^T)
    gemm_bf_kernel<<<dim3(DD/128, SS/128, BB), blk, SM_TOTAL>>>(
        attn, nullptr, qT, nullptr, classical, iface, out,
        nullptr, nullptr, nullptr, nullptr,
        DD, SS, SS, SS,
        (long)SS*SS, (long)DD*SS, (long)SS*DD, 3);
}

// round 9
// speedup vs baseline: 7.6316x; 1.0044x over previous
#include <cuda_runtime.h>
#include <cuda_bf16.h>
#include <math.h>
#include <stdint.h>

// Problem constants
#define BB 4
#define SS 2048
#define DD 1024
#define MS (BB*SS)          // 8192 rows

#define KC  64              // K bf16 elements per chunk (= 128B smem rows)
#define SM_BUF 16384        // one 128x64 bf16 tile
#define NSTAGE 3
#define SM_STAGE (2*SM_BUF)
#define SM_TOTAL (NSTAGE*SM_STAGE)   // 96 KB

// Scratch (no allocations allowed -> device globals)
__device__ __nv_bfloat16 g_cls_bf[MS*DD];            // 16 MB
__device__ __nv_bfloat16 g_q_bf[MS*DD];              // 16 MB
__device__ __nv_bfloat16 g_Wc_bf[DD*DD];             // 2 MB
__device__ __nv_bfloat16 g_Wq_bf[DD*DD];             // 2 MB
__device__ __nv_bfloat16 g_Wg_bf[DD*2*DD];           // 4 MB
__device__ __nv_bfloat16 g_cproj[MS*DD];             // 16 MB
__device__ __nv_bfloat16 g_qproj[MS*DD];             // 16 MB
__device__ __nv_bfloat16 g_qT[(size_t)BB*DD*SS];     // 16 MB
__device__ __nv_bfloat16 g_attn[(size_t)BB*SS*SS];   // 32 MB
__device__ float g_iface[MS*DD];                     // 32 MB
__device__ float g_sim[(size_t)BB*SS*SS];            // 64 MB

// ---------------------------------------------------------------------------
__device__ __forceinline__ uint32_t smem_u32(const void* p) {
    uint32_t a;
    asm("{ .reg .u64 t; cvta.to.shared.u64 t, %1; cvt.u32.u64 %0, t; }" : "=r"(a) : "l"(p));
    return a;
}
__device__ __forceinline__ uint32_t pack_bf16(float lo, float hi) {
    uint32_t u;
    asm("cvt.rn.bf16x2.f32 %0, %1, %2;" : "=r"(u) : "f"(hi), "f"(lo));
    return u;
}

#define CP_COMMIT() asm volatile("cp.async.commit_group;" ::: "memory")
#define CP_WAIT(n)  asm volatile("cp.async.wait_group %0;" :: "n"(n) : "memory")

#define LDSM4(d, addr) \
    asm volatile("ldmatrix.sync.aligned.m8n8.x4.shared.b16 {%0,%1,%2,%3}, [%4];" \
        : "=r"((d)[0]), "=r"((d)[1]), "=r"((d)[2]), "=r"((d)[3]) : "r"(addr))

__device__ __forceinline__ void mma16(float* c, const uint32_t* a, const uint32_t* b) {
    asm volatile("mma.sync.aligned.m16n8k16.row.col.f32.bf16.bf16.f32 "
                 "{%0,%1,%2,%3}, {%4,%5,%6,%7}, {%8,%9}, {%0,%1,%2,%3};"
                 : "+f"(c[0]), "+f"(c[1]), "+f"(c[2]), "+f"(c[3])
                 : "r"(a[0]), "r"(a[1]), "r"(a[2]), "r"(a[3]), "r"(b[0]), "r"(b[1]));
}

// Issue one chunk's A+B loads (16 cp.async per thread @128 threads), 1 commit.
__device__ __forceinline__ void issue_chunk(const __nv_bfloat16* __restrict__ baseA,
                                            const __nv_bfloat16* __restrict__ baseB,
                                            const int* rowoffA, const int* rowoffB,
                                            const uint32_t* smoff, uint32_t stg) {
    #pragma unroll
    for (int i = 0; i < 8; i++)
        asm volatile("cp.async.cg.shared.global [%0], [%1], 16;"
            :: "r"(stg + smoff[i]), "l"(baseA + rowoffA[i]));
    #pragma unroll
    for (int i = 0; i < 8; i++)
        asm volatile("cp.async.cg.shared.global [%0], [%1], 16;"
            :: "r"(stg + SM_BUF + smoff[i]), "l"(baseB + rowoffB[i]));
    CP_COMMIT();
}

// ---------------------------------------------------------------------------
// NT bf16 tensor-core GEMM: acc[m,n] = sum_k A[m,k] * B[n,k]  (fp32 accum)
// 128 threads, CTA tile 128x128, warp tile 64x64 (2x2 warp grid).
// A-concat: chunk k >= Ksplit reads A2[m, k-Ksplit] (same lda).
// Dual-set: if Ad != null and blockIdx.z == 1, use (Ad,Bd,biasd,Cd) instead.
// mode 0: bf16 store of (acc+bias)   1: fp32 sigmoid(acc+bias)
// mode 2: fp32 raw                   3: fp32 Cls + Ifc*acc
// ---------------------------------------------------------------------------
__global__ __launch_bounds__(128, 2)
void gemm_bf_kernel(const __nv_bfloat16* __restrict__ A,
                    const __nv_bfloat16* __restrict__ A2,
                    const __nv_bfloat16* __restrict__ B,
                    const float* __restrict__ bias,
                    const float* __restrict__ Cls,
                    const float* __restrict__ Ifc,
                    void* __restrict__ Cout,
                    const __nv_bfloat16* __restrict__ Ad,
                    const __nv_bfloat16* __restrict__ Bd,
                    const float* __restrict__ biasd,
                    void* __restrict__ Cd,
                    int N, int K, int Ksplit, int lda,
                    long As_batch, long Bs_batch, long Cs_batch,
                    int mode)
{
    extern __shared__ char smem[];
    uint32_t sb = smem_u32(smem);

    int tid  = threadIdx.x;
    int wid  = tid >> 5;
    int lane = tid & 31;
    int g    = lane >> 2;      // 0..7
    int tig  = lane & 3;       // 0..3
    int mw   = (wid >> 1) * 64;   // 2 row groups
    int nw   = (wid & 1) * 64;    // 2 col groups

    int bz = blockIdx.z;
    if (Ad && bz == 1) {       // dual projection mode
        A = Ad; B = Bd; bias = biasd; Cout = Cd;
        bz = 0;
    }
    A += bz * As_batch;
    if (A2) A2 += bz * As_batch;
    B += bz * Bs_batch;
    if (Cls) Cls += bz * Cs_batch;
    if (Ifc) Ifc += bz * Cs_batch;

    int row0 = blockIdx.y * 128;
    int col0 = blockIdx.x * 128;

    // Hoisted per-thread load offsets: thread handles 8 rows for A and B.
    int rowoffA[8], rowoffB[8];
    uint32_t smoff[8];
    #pragma unroll
    for (int i = 0; i < 8; i++) {
        int idx = i * 128 + tid;
        int row = idx >> 3;
        int seg = idx & 7;
        rowoffA[i] = (row0 + row) * lda + seg * 8;
        rowoffB[i] = (col0 + row) * K + seg * 8;
        smoff[i]   = (uint32_t)(row * 128 + ((seg ^ (row & 7)) << 4));
    }

    // ldmatrix addressing: lane t serves matrix q=t>>3, row r=t&7.
    int r  = lane & 7;
    int q  = lane >> 3;
    int ql = q & 1;
    int qh = q >> 1;
    uint32_t segoff[4];
    #pragma unroll
    for (int ks = 0; ks < 4; ks++)
        segoff[ks] = (uint32_t)((((2 * ks + qh) ^ r) << 4));
    uint32_t ArowB = sb + (uint32_t)((mw + ql * 8 + r) * 128);
    uint32_t BrowB = sb + SM_BUF + (uint32_t)((nw + ql * 8 + r) * 128);

    float acc[4][8][4];
    #pragma unroll
    for (int i = 0; i < 4; i++)
        #pragma unroll
        for (int j = 0; j < 8; j++)
            #pragma unroll
            for (int p = 0; p < 4; p++) acc[i][j][p] = 0.0f;

    const int NC = K / KC;

    // prologue: chunks 0,1 -> stages 0,1
    #pragma unroll
    for (int p = 0; p < 2; p++) {
        int kt = p * KC;
        const __nv_bfloat16* bA = (kt < Ksplit) ? (A + kt) : (A2 + (kt - Ksplit));
        issue_chunk(bA, B + kt, rowoffA, rowoffB, smoff, sb + p * SM_STAGE);
    }

    int stage = 0;
    for (int ch = 0; ch < NC; ch++) {
        if (ch + 1 < NC) { CP_WAIT(1); } else { CP_WAIT(0); }
        __syncthreads();

        uint32_t At = ArowB + stage * SM_STAGE;
        uint32_t Bt = BrowB + stage * SM_STAGE;

        #pragma unroll
        for (int ks = 0; ks < 4; ks++) {          // 4 x k16 = 64
            uint32_t so = segoff[ks];
            uint32_t af[4][4];
            #pragma unroll
            for (int i = 0; i < 4; i++)
                LDSM4(af[i], At + i * 2048 + so);
            uint32_t bf[8][2];
            #pragma unroll
            for (int j2 = 0; j2 < 4; j2++) {
                uint32_t t[4];
                LDSM4(t, Bt + j2 * 2048 + so);
                bf[2 * j2][0]     = t[0];
                bf[2 * j2 + 1][0] = t[1];
                bf[2 * j2][1]     = t[2];
                bf[2 * j2 + 1][1] = t[3];
            }
            #pragma unroll
            for (int i = 0; i < 4; i++)
                #pragma unroll
                for (int j = 0; j < 8; j++)
                    mma16(acc[i][j], af[i], bf[j]);
        }

        if (ch + 2 < NC) {
            int kt = (ch + 2) * KC;
            const __nv_bfloat16* bA = (kt < Ksplit) ? (A + kt) : (A2 + (kt - Ksplit));
            int ns = stage + 2; if (ns >= NSTAGE) ns -= NSTAGE;
            issue_chunk(bA, B + kt, rowoffA, rowoffB, smoff, sb + ns * SM_STAGE);
        }
        stage++; if (stage >= NSTAGE) stage = 0;
    }

    // Epilogue: c0,c1 at (row g, cols 2tig..), c2,c3 at row g+8
    #pragma unroll
    for (int i = 0; i < 4; i++) {
        int rA = row0 + mw + 16 * i + g;
        int rB = rA + 8;
        #pragma unroll
        for (int j = 0; j < 8; j++) {
            int c = col0 + nw + 8 * j + 2 * tig;
            float2 v0 = make_float2(acc[i][j][0], acc[i][j][1]);
            float2 v1 = make_float2(acc[i][j][2], acc[i][j][3]);

            if (mode == 0) {
                float2 bb = *reinterpret_cast<const float2*>(bias + c);
                __nv_bfloat16* Cb = (__nv_bfloat16*)Cout + bz * Cs_batch;
                *reinterpret_cast<uint32_t*>(Cb + (long)rA * N + c) =
                    pack_bf16(v0.x + bb.x, v0.y + bb.y);
                *reinterpret_cast<uint32_t*>(Cb + (long)rB * N + c) =
                    pack_bf16(v1.x + bb.x, v1.y + bb.y);
            } else {
                float* Cf = (float*)Cout + bz * Cs_batch;
                if (mode == 1) {
                    float2 bb = *reinterpret_cast<const float2*>(bias + c);
                    v0.x = 1.0f / (1.0f + __expf(-(v0.x + bb.x)));
                    v0.y = 1.0f / (1.0f + __expf(-(v0.y + bb.y)));
                    v1.x = 1.0f / (1.0f + __expf(-(v1.x + bb.x)));
                    v1.y = 1.0f / (1.0f + __expf(-(v1.y + bb.y)));
                } else if (mode == 3) {
                    long i0 = (long)rA * N + c;
                    long i1 = (long)rB * N + c;
                    float2 cl0 = *reinterpret_cast<const float2*>(Cls + i0);
                    float2 cl1 = *reinterpret_cast<const float2*>(Cls + i1);
                    float2 fi0 = *reinterpret_cast<const float2*>(Ifc + i0);
                    float2 fi1 = *reinterpret_cast<const float2*>(Ifc + i1);
                    v0.x = cl0.x + fi0.x * v0.x;  v0.y = cl0.y + fi0.y * v0.y;
                    v1.x = cl1.x + fi1.x * v1.x;  v1.y = cl1.y + fi1.y * v1.y;
                }
                *reinterpret_cast<float2*>(Cf + (long)rA * N + c) = v0;
                *reinterpret_cast<float2*>(Cf + (long)rB * N + c) = v1;
            }
        }
    }
}

// ---------------------------------------------------------------------------
// Fused fp32 -> bf16 conversion of all five inputs (float4 grid-stride).
// ---------------------------------------------------------------------------
#define N4_CLS ((long)MS*DD/4)
#define N4_W   ((long)DD*DD/4)
#define N4_WG  ((long)DD*2*DD/4)
__global__ __launch_bounds__(256)
void tobf16_all_kernel(const float* __restrict__ cls, const float* __restrict__ q,
                       const float* __restrict__ Wc, const float* __restrict__ Wq,
                       const float* __restrict__ Wg,
                       __nv_bfloat16* __restrict__ cls_o, __nv_bfloat16* __restrict__ q_o,
                       __nv_bfloat16* __restrict__ Wc_o, __nv_bfloat16* __restrict__ Wq_o,
                       __nv_bfloat16* __restrict__ Wg_o)
{
    const long total = 2 * N4_CLS + 2 * N4_W + N4_WG;
    long i = (long)blockIdx.x * blockDim.x + threadIdx.x;
    long stride = (long)gridDim.x * blockDim.x;
    for (; i < total; i += stride) {
        const float* src; __nv_bfloat16* dst; long off;
        if (i < N4_CLS)                        { src = cls; dst = cls_o; off = i; }
        else if (i < 2 * N4_CLS)               { src = q;   dst = q_o;   off = i - N4_CLS; }
        else if (i < 2 * N4_CLS + N4_W)        { src = Wc;  dst = Wc_o;  off = i - 2 * N4_CLS; }
        else if (i < 2 * N4_CLS + 2 * N4_W)    { src = Wq;  dst = Wq_o;  off = i - 2 * N4_CLS - N4_W; }
        else                                   { src = Wg;  dst = Wg_o;  off = i - 2 * N4_CLS - 2 * N4_W; }
        float4 v = reinterpret_cast<const float4*>(src)[off];
        uint2 o;
        o.x = pack_bf16(v.x, v.y);
        o.y = pack_bf16(v.z, v.w);
        reinterpret_cast<uint2*>(dst)[off] = o;
    }
}

// ---------------------------------------------------------------------------
// Transpose per batch: fp32 in [S,D] -> bf16 out [D,S]
// ---------------------------------------------------------------------------
__global__ __launch_bounds__(256)
void transpose_kernel(const float* __restrict__ in, __nv_bfloat16* __restrict__ out)
{
    __shared__ float t[32][33];
    int bz = blockIdx.z;
    in  += (long)bz * SS * DD;
    out += (long)bz * DD * SS;

    int d0 = blockIdx.x * 32;
    int s0 = blockIdx.y * 32;
    int tx = threadIdx.x & 31;
    int ty = threadIdx.x >> 5;   // 0..7

    #pragma unroll
    for (int i = 0; i < 4; i++) {
        int s = s0 + ty + i * 8;
        t[ty + i * 8][tx] = in[(long)s * DD + d0 + tx];
    }
    __syncthreads();
    #pragma unroll
    for (int i = 0; i < 4; i++) {
        int d = d0 + ty + i * 8;
        out[(long)d * SS + s0 + tx] = __float2bfloat16(t[tx][ty + i * 8]);
    }
}

// ---------------------------------------------------------------------------
// Row softmax over S=2048, scale (1/sqrt(D))/T; fp32 in, bf16 out. float4 I/O.
// ---------------------------------------------------------------------------
__global__ __launch_bounds__(256)
void softmax_kernel(const float* __restrict__ sim, __nv_bfloat16* __restrict__ attn,
                    const float* __restrict__ temp)
{
    __shared__ float red_max[8];
    __shared__ float red_sum[8];

    long row = blockIdx.x;
    const float4* p4 = reinterpret_cast<const float4*>(sim + row * (long)SS);
    __nv_bfloat16* po = attn + row * (long)SS;
    int tid  = threadIdx.x;
    int lane = tid & 31;
    int wid  = tid >> 5;

    float s = (1.0f / 32.0f) / (*temp);

    float4 a = p4[tid];
    float4 b = p4[tid + 256];
    float v[8] = {a.x * s, a.y * s, a.z * s, a.w * s,
                  b.x * s, b.y * s, b.z * s, b.w * s};
    float mx = v[0];
    #pragma unroll
    for (int i = 1; i < 8; i++) mx = fmaxf(mx, v[i]);
    #pragma unroll
    for (int o = 16; o > 0; o >>= 1)
        mx = fmaxf(mx, __shfl_xor_sync(0xffffffffu, mx, o));
    if (lane == 0) red_max[wid] = mx;
    __syncthreads();
    mx = red_max[0];
    #pragma unroll
    for (int w = 1; w < 8; w++) mx = fmaxf(mx, red_max[w]);

    float sum = 0.0f;
    #pragma unroll
    for (int i = 0; i < 8; i++) {
        v[i] = __expf(v[i] - mx);
        sum += v[i];
    }
    #pragma unroll
    for (int o = 16; o > 0; o >>= 1)
        sum += __shfl_xor_sync(0xffffffffu, sum, o);
    if (lane == 0) red_sum[wid] = sum;
    __syncthreads();
    sum = 0.0f;
    #pragma unroll
    for (int w = 0; w < 8; w++) sum += red_sum[w];

    float inv = 1.0f / sum;
    uint2 o0, o1;
    o0.x = pack_bf16(v[0] * inv, v[1] * inv);
    o0.y = pack_bf16(v[2] * inv, v[3] * inv);
    o1.x = pack_bf16(v[4] * inv, v[5] * inv);
    o1.y = pack_bf16(v[6] * inv, v[7] * inv);
    reinterpret_cast<uint2*>(po)[tid] = o0;
    reinterpret_cast<uint2*>(po)[tid + 256] = o1;
}

// ---------------------------------------------------------------------------
extern "C" void kernel_launch(void* const* d_in, const int* in_sizes, int n_in,
                              void* d_out, int out_size)
{
    const float* classical = (const float*)d_in[0];
    const float* quantum   = (const float*)d_in[1];
    const float* Wc        = (const float*)d_in[2];
    const float* bc        = (const float*)d_in[3];
    const float* Wq        = (const float*)d_in[4];
    const float* bq        = (const float*)d_in[5];
    const float* Wg        = (const float*)d_in[6];
    const float* bg        = (const float*)d_in[7];
    const float* temp      = (const float*)d_in[8];
    float* out             = (float*)d_out;

    __nv_bfloat16 *cls_bf, *q_bf, *Wc_bf, *Wq_bf, *Wg_bf, *cproj, *qproj, *qT, *attn;
    float *iface, *sim;
    cudaGetSymbolAddress((void**)&cls_bf, g_cls_bf);
    cudaGetSymbolAddress((void**)&q_bf,   g_q_bf);
    cudaGetSymbolAddress((void**)&Wc_bf,  g_Wc_bf);
    cudaGetSymbolAddress((void**)&Wq_bf,  g_Wq_bf);
    cudaGetSymbolAddress((void**)&Wg_bf,  g_Wg_bf);
    cudaGetSymbolAddress((void**)&cproj,  g_cproj);
    cudaGetSymbolAddress((void**)&qproj,  g_qproj);
    cudaGetSymbolAddress((void**)&qT,     g_qT);
    cudaGetSymbolAddress((void**)&attn,   g_attn);
    cudaGetSymbolAddress((void**)&iface,  g_iface);
    cudaGetSymbolAddress((void**)&sim,    g_sim);

    cudaFuncSetAttribute(gemm_bf_kernel,
                         cudaFuncAttributeMaxDynamicSharedMemorySize, SM_TOTAL);

    dim3 blk(128);

    // Convert all inputs to bf16 (single launch)
    tobf16_all_kernel<<<2048, 256>>>(classical, quantum, Wc, Wq, Wg,
                                     cls_bf, q_bf, Wc_bf, Wq_bf, Wg_bf);

    // 0) qT[b] = bf16(quantum[b]^T)  [D,S]
    transpose_kernel<<<dim3(DD/32, SS/32, BB), 256>>>(quantum, qT);

    // 1+2) fused dual projection:
    //   z=0: cproj = bf16(classical @ Wc^T + bc)
    //   z=1: qproj = bf16(quantum   @ Wq^T + bq)
    gemm_bf_kernel<<<dim3(DD/128, MS/128, 2), blk, SM_TOTAL>>>(
        cls_bf, nullptr, Wc_bf, bc, nullptr, nullptr, cproj,
        q_bf, Wq_bf, bq, qproj,
        DD, DD, DD, DD, 0, 0, 0, 0);

    // 3) iface = sigmoid([cproj|qproj] @ Wg^T + bg), K=2048 split at 1024
    gemm_bf_kernel<<<dim3(DD/128, MS/128, 1), blk, SM_TOTAL>>>(
        cproj, qproj, Wg_bf, bg, nullptr, nullptr, iface,
        nullptr, nullptr, nullptr, nullptr,
        DD, 2*DD, DD, DD, 0, 0, 0, 1);

    // 4) sim[b] = cproj[b] @ qproj[b]^T  (raw fp32; scale folded into softmax)
    gemm_bf_kernel<<<dim3(SS/128, SS/128, BB), blk, SM_TOTAL>>>(
        cproj, nullptr, qproj, nullptr, nullptr, nullptr, sim,
        nullptr, nullptr, nullptr, nullptr,
        SS, DD, DD, DD,
        (long)SS*DD, (long)SS*DD, (long)SS*SS, 2);

    // 5) softmax -> bf16 attn
    softmax_kernel<<<BB*SS, 256>>>(sim, attn, temp);

    // 6) out = classical + iface * (attn[b] @ qT[b]^T)
    gemm_bf_kernel<<<dim3(DD/128, SS/128, BB), blk, SM_TOTAL>>>(
        attn, nullptr, qT, nullptr, classical, iface, out,
        nullptr, nullptr, nullptr, nullptr,
        DD, SS, SS, SS,
        (long)SS*SS, (long)DD*SS, (long)SS*DD, 3);
}

// round 10
// speedup vs baseline: 7.6357x; 1.0005x over previous
#include <cuda_runtime.h>
#include <cuda_bf16.h>
#include <math.h>
#include <stdint.h>

// Problem constants
#define BB 4
#define SS 2048
#define DD 1024
#define MS (BB*SS)          // 8192 rows

#define KC  64              // K bf16 elements per chunk (= 128B smem rows)
#define SM_BUF 16384        // one 128x64 bf16 tile
#define NSTAGE 3
#define SM_STAGE (2*SM_BUF)
#define SM_TOTAL (NSTAGE*SM_STAGE)   // 96 KB

// Scratch (no allocations allowed -> device globals)
__device__ __nv_bfloat16 g_cls_bf[MS*DD];            // 16 MB
__device__ __nv_bfloat16 g_q_bf[MS*DD];              // 16 MB
__device__ __nv_bfloat16 g_Wc_bf[DD*DD];             // 2 MB
__device__ __nv_bfloat16 g_Wq_bf[DD*DD];             // 2 MB
__device__ __nv_bfloat16 g_Wg_bf[DD*2*DD];           // 4 MB
__device__ __nv_bfloat16 g_cproj[MS*DD];             // 16 MB
__device__ __nv_bfloat16 g_qproj[MS*DD];             // 16 MB
__device__ __nv_bfloat16 g_qT[(size_t)BB*DD*SS];     // 16 MB
__device__ __nv_bfloat16 g_attn[(size_t)BB*SS*SS];   // 32 MB
__device__ float g_iface[MS*DD];                     // 32 MB
__device__ float g_sim[(size_t)BB*SS*SS];            // 64 MB

// ---------------------------------------------------------------------------
__device__ __forceinline__ uint32_t smem_u32(const void* p) {
    uint32_t a;
    asm("{ .reg .u64 t; cvta.to.shared.u64 t, %1; cvt.u32.u64 %0, t; }" : "=r"(a) : "l"(p));
    return a;
}
__device__ __forceinline__ uint32_t pack_bf16(float lo, float hi) {
    uint32_t u;
    asm("cvt.rn.bf16x2.f32 %0, %1, %2;" : "=r"(u) : "f"(hi), "f"(lo));
    return u;
}

#define CP_COMMIT() asm volatile("cp.async.commit_group;" ::: "memory")
#define CP_WAIT(n)  asm volatile("cp.async.wait_group %0;" :: "n"(n) : "memory")

#define LDSM4(d, addr) \
    asm volatile("ldmatrix.sync.aligned.m8n8.x4.shared.b16 {%0,%1,%2,%3}, [%4];" \
        : "=r"((d)[0]), "=r"((d)[1]), "=r"((d)[2]), "=r"((d)[3]) : "r"(addr))

__device__ __forceinline__ void mma16(float* c, const uint32_t* a, const uint32_t* b) {
    asm volatile("mma.sync.aligned.m16n8k16.row.col.f32.bf16.bf16.f32 "
                 "{%0,%1,%2,%3}, {%4,%5,%6,%7}, {%8,%9}, {%0,%1,%2,%3};"
                 : "+f"(c[0]), "+f"(c[1]), "+f"(c[2]), "+f"(c[3])
                 : "r"(a[0]), "r"(a[1]), "r"(a[2]), "r"(a[3]), "r"(b[0]), "r"(b[1]));
}

// Issue one chunk's A+B loads (8 cp.async per thread @256 threads), 1 commit.
__device__ __forceinline__ void issue_chunk(const __nv_bfloat16* __restrict__ baseA,
                                            const __nv_bfloat16* __restrict__ baseB,
                                            const int* rowoffA, const int* rowoffB,
                                            const uint32_t* smoff, uint32_t stg) {
    #pragma unroll
    for (int i = 0; i < 4; i++)
        asm volatile("cp.async.cg.shared.global [%0], [%1], 16;"
            :: "r"(stg + smoff[i]), "l"(baseA + rowoffA[i]));
    #pragma unroll
    for (int i = 0; i < 4; i++)
        asm volatile("cp.async.cg.shared.global [%0], [%1], 16;"
            :: "r"(stg + SM_BUF + smoff[i]), "l"(baseB + rowoffB[i]));
    CP_COMMIT();
}

// ---------------------------------------------------------------------------
// NT bf16 tensor-core GEMM: acc[m,n] = sum_k A[m,k] * B[n,k]  (fp32 accum)
// 256 threads, CTA tile 128x128, warp tile 64x32 (2x4 warp grid).
// A-concat: chunk k >= Ksplit reads A2[m, k-Ksplit] (same lda).
// Dual-set: if Ad != null and blockIdx.z == 1, use (Ad,Bd,biasd,Cd) instead.
// mode 0: bf16 store of (acc+bias)   1: fp32 sigmoid(acc+bias)
// mode 2: fp32 raw                   3: fp32 Cls + Ifc*acc
// ---------------------------------------------------------------------------
__global__ __launch_bounds__(256, 2)
void gemm_bf_kernel(const __nv_bfloat16* __restrict__ A,
                    const __nv_bfloat16* __restrict__ A2,
                    const __nv_bfloat16* __restrict__ B,
                    const float* __restrict__ bias,
                    const float* __restrict__ Cls,
                    const float* __restrict__ Ifc,
                    void* __restrict__ Cout,
                    const __nv_bfloat16* __restrict__ Ad,
                    const __nv_bfloat16* __restrict__ Bd,
                    const float* __restrict__ biasd,
                    void* __restrict__ Cd,
                    int N, int K, int Ksplit, int lda,
                    long As_batch, long Bs_batch, long Cs_batch,
                    int mode)
{
    extern __shared__ char smem[];
    uint32_t sb = smem_u32(smem);

    int tid  = threadIdx.x;
    int wid  = tid >> 5;
    int lane = tid & 31;
    int g    = lane >> 2;      // 0..7
    int tig  = lane & 3;       // 0..3
    int mw   = (wid >> 2) * 64;   // 2 row groups
    int nw   = (wid & 3) * 32;    // 4 col groups

    int bz = blockIdx.z;
    if (Ad && bz == 1) {       // dual projection mode
        A = Ad; B = Bd; bias = biasd; Cout = Cd;
        bz = 0;
    }
    A += bz * As_batch;
    if (A2) A2 += bz * As_batch;
    B += bz * Bs_batch;
    if (Cls) Cls += bz * Cs_batch;
    if (Ifc) Ifc += bz * Cs_batch;

    int row0 = blockIdx.y * 128;
    int col0 = blockIdx.x * 128;

    // Hoisted per-thread load offsets: thread handles 4 rows for A and B.
    int rowoffA[4], rowoffB[4];
    uint32_t smoff[4];
    #pragma unroll
    for (int i = 0; i < 4; i++) {
        int idx = i * 256 + tid;
        int row = idx >> 3;
        int seg = idx & 7;
        rowoffA[i] = (row0 + row) * lda + seg * 8;
        rowoffB[i] = (col0 + row) * K + seg * 8;
        smoff[i]   = (uint32_t)(row * 128 + ((seg ^ (row & 7)) << 4));
    }

    // ldmatrix addressing: lane t serves matrix q=t>>3, row r=t&7.
    int r  = lane & 7;
    int q  = lane >> 3;
    int ql = q & 1;
    int qh = q >> 1;
    uint32_t segoff[4];
    #pragma unroll
    for (int ks = 0; ks < 4; ks++)
        segoff[ks] = (uint32_t)((((2 * ks + qh) ^ r) << 4));
    uint32_t ArowB = sb + (uint32_t)((mw + ql * 8 + r) * 128);
    uint32_t BrowB = sb + SM_BUF + (uint32_t)((nw + ql * 8 + r) * 128);

    float acc[4][4][4];
    #pragma unroll
    for (int i = 0; i < 4; i++)
        #pragma unroll
        for (int j = 0; j < 4; j++)
            #pragma unroll
            for (int p = 0; p < 4; p++) acc[i][j][p] = 0.0f;

    const int NC = K / KC;

    // prologue: chunks 0,1 -> stages 0,1
    #pragma unroll
    for (int p = 0; p < 2; p++) {
        int kt = p * KC;
        const __nv_bfloat16* bA = (kt < Ksplit) ? (A + kt) : (A2 + (kt - Ksplit));
        issue_chunk(bA, B + kt, rowoffA, rowoffB, smoff, sb + p * SM_STAGE);
    }

    int stage = 0;
    for (int ch = 0; ch < NC; ch++) {
        if (ch + 1 < NC) { CP_WAIT(1); } else { CP_WAIT(0); }
        __syncthreads();

        uint32_t At = ArowB + stage * SM_STAGE;
        uint32_t Bt = BrowB + stage * SM_STAGE;

        #pragma unroll
        for (int ks = 0; ks < 4; ks++) {          // 4 x k16 = 64
            uint32_t so = segoff[ks];
            uint32_t af[4][4];
            #pragma unroll
            for (int i = 0; i < 4; i++)
                LDSM4(af[i], At + i * 2048 + so);
            uint32_t bf[4][2];
            #pragma unroll
            for (int j2 = 0; j2 < 2; j2++) {
                uint32_t t[4];
                LDSM4(t, Bt + j2 * 2048 + so);
                bf[2 * j2][0]     = t[0];
                bf[2 * j2 + 1][0] = t[1];
                bf[2 * j2][1]     = t[2];
                bf[2 * j2 + 1][1] = t[3];
            }
            #pragma unroll
            for (int i = 0; i < 4; i++)
                #pragma unroll
                for (int j = 0; j < 4; j++)
                    mma16(acc[i][j], af[i], bf[j]);
        }

        if (ch + 2 < NC) {
            int kt = (ch + 2) * KC;
            const __nv_bfloat16* bA = (kt < Ksplit) ? (A + kt) : (A2 + (kt - Ksplit));
            int ns = stage + 2; if (ns >= NSTAGE) ns -= NSTAGE;
            issue_chunk(bA, B + kt, rowoffA, rowoffB, smoff, sb + ns * SM_STAGE);
        }
        stage++; if (stage >= NSTAGE) stage = 0;
    }

    // Epilogue: c0,c1 at (row g, cols 2tig..), c2,c3 at row g+8
    #pragma unroll
    for (int i = 0; i < 4; i++) {
        int rA = row0 + mw + 16 * i + g;
        int rB = rA + 8;
        #pragma unroll
        for (int j = 0; j < 4; j++) {
            int c = col0 + nw + 8 * j + 2 * tig;
            float2 v0 = make_float2(acc[i][j][0], acc[i][j][1]);
            float2 v1 = make_float2(acc[i][j][2], acc[i][j][3]);

            if (mode == 0) {
                float2 bb = *reinterpret_cast<const float2*>(bias + c);
                __nv_bfloat16* Cb = (__nv_bfloat16*)Cout + bz * Cs_batch;
                *reinterpret_cast<uint32_t*>(Cb + (long)rA * N + c) =
                    pack_bf16(v0.x + bb.x, v0.y + bb.y);
                *reinterpret_cast<uint32_t*>(Cb + (long)rB * N + c) =
                    pack_bf16(v1.x + bb.x, v1.y + bb.y);
            } else {
                float* Cf = (float*)Cout + bz * Cs_batch;
                if (mode == 1) {
                    float2 bb = *reinterpret_cast<const float2*>(bias + c);
                    v0.x = 1.0f / (1.0f + __expf(-(v0.x + bb.x)));
                    v0.y = 1.0f / (1.0f + __expf(-(v0.y + bb.y)));
                    v1.x = 1.0f / (1.0f + __expf(-(v1.x + bb.x)));
                    v1.y = 1.0f / (1.0f + __expf(-(v1.y + bb.y)));
                } else if (mode == 3) {
                    long i0 = (long)rA * N + c;
                    long i1 = (long)rB * N + c;
                    float2 cl0 = *reinterpret_cast<const float2*>(Cls + i0);
                    float2 cl1 = *reinterpret_cast<const float2*>(Cls + i1);
                    float2 fi0 = *reinterpret_cast<const float2*>(Ifc + i0);
                    float2 fi1 = *reinterpret_cast<const float2*>(Ifc + i1);
                    v0.x = cl0.x + fi0.x * v0.x;  v0.y = cl0.y + fi0.y * v0.y;
                    v1.x = cl1.x + fi1.x * v1.x;  v1.y = cl1.y + fi1.y * v1.y;
                }
                *reinterpret_cast<float2*>(Cf + (long)rA * N + c) = v0;
                *reinterpret_cast<float2*>(Cf + (long)rB * N + c) = v1;
            }
        }
    }
}

// ---------------------------------------------------------------------------
// Fused fp32 -> bf16 conversion of all five inputs.
// Direct index: ONE float4 per thread, no loop (latency hidden by TLP).
// Total float4 = 2*N4_CLS + 2*N4_W + N4_WG = 5,242,880 -> grid 20480 x 256.
// ---------------------------------------------------------------------------
#define N4_CLS ((long)MS*DD/4)
#define N4_W   ((long)DD*DD/4)
#define N4_WG  ((long)DD*2*DD/4)
#define N4_TOTAL (2*N4_CLS + 2*N4_W + N4_WG)
__global__ __launch_bounds__(256)
void tobf16_all_kernel(const float* __restrict__ cls, const float* __restrict__ q,
                       const float* __restrict__ Wc, const float* __restrict__ Wq,
                       const float* __restrict__ Wg,
                       __nv_bfloat16* __restrict__ cls_o, __nv_bfloat16* __restrict__ q_o,
                       __nv_bfloat16* __restrict__ Wc_o, __nv_bfloat16* __restrict__ Wq_o,
                       __nv_bfloat16* __restrict__ Wg_o)
{
    long i = (long)blockIdx.x * 256 + threadIdx.x;
    const float* src; __nv_bfloat16* dst; long off;
    if (i < N4_CLS)                        { src = cls; dst = cls_o; off = i; }
    else if (i < 2 * N4_CLS)               { src = q;   dst = q_o;   off = i - N4_CLS; }
    else if (i < 2 * N4_CLS + N4_W)        { src = Wc;  dst = Wc_o;  off = i - 2 * N4_CLS; }
    else if (i < 2 * N4_CLS + 2 * N4_W)    { src = Wq;  dst = Wq_o;  off = i - 2 * N4_CLS - N4_W; }
    else                                   { src = Wg;  dst = Wg_o;  off = i - 2 * N4_CLS - 2 * N4_W; }
    float4 v = reinterpret_cast<const float4*>(src)[off];
    uint2 o;
    o.x = pack_bf16(v.x, v.y);
    o.y = pack_bf16(v.z, v.w);
    reinterpret_cast<uint2*>(dst)[off] = o;
}

// ---------------------------------------------------------------------------
// Transpose per batch: fp32 in [S,D] -> bf16 out [D,S]
// ---------------------------------------------------------------------------
__global__ __launch_bounds__(256)
void transpose_kernel(const float* __restrict__ in, __nv_bfloat16* __restrict__ out)
{
    __shared__ float t[32][33];
    int bz = blockIdx.z;
    in  += (long)bz * SS * DD;
    out += (long)bz * DD * SS;

    int d0 = blockIdx.x * 32;
    int s0 = blockIdx.y * 32;
    int tx = threadIdx.x & 31;
    int ty = threadIdx.x >> 5;   // 0..7

    #pragma unroll
    for (int i = 0; i < 4; i++) {
        int s = s0 + ty + i * 8;
        t[ty + i * 8][tx] = in[(long)s * DD + d0 + tx];
    }
    __syncthreads();
    #pragma unroll
    for (int i = 0; i < 4; i++) {
        int d = d0 + ty + i * 8;
        out[(long)d * SS + s0 + tx] = __float2bfloat16(t[tx][ty + i * 8]);
    }
}

// ---------------------------------------------------------------------------
// Row softmax over S=2048, scale (1/sqrt(D))/T; fp32 in, bf16 out. float4 I/O.
// ---------------------------------------------------------------------------
__global__ __launch_bounds__(256)
void softmax_kernel(const float* __restrict__ sim, __nv_bfloat16* __restrict__ attn,
                    const float* __restrict__ temp)
{
    __shared__ float red_max[8];
    __shared__ float red_sum[8];

    long row = blockIdx.x;
    const float4* p4 = reinterpret_cast<const float4*>(sim + row * (long)SS);
    __nv_bfloat16* po = attn + row * (long)SS;
    int tid  = threadIdx.x;
    int lane = tid & 31;
    int wid  = tid >> 5;

    float s = (1.0f / 32.0f) / (*temp);

    float4 a = p4[tid];
    float4 b = p4[tid + 256];
    float v[8] = {a.x * s, a.y * s, a.z * s, a.w * s,
                  b.x * s, b.y * s, b.z * s, b.w * s};
    float mx = v[0];
    #pragma unroll
    for (int i = 1; i < 8; i++) mx = fmaxf(mx, v[i]);
    #pragma unroll
    for (int o = 16; o > 0; o >>= 1)
        mx = fmaxf(mx, __shfl_xor_sync(0xffffffffu, mx, o));
    if (lane == 0) red_max[wid] = mx;
    __syncthreads();
    mx = red_max[0];
    #pragma unroll
    for (int w = 1; w < 8; w++) mx = fmaxf(mx, red_max[w]);

    float sum = 0.0f;
    #pragma unroll
    for (int i = 0; i < 8; i++) {
        v[i] = __expf(v[i] - mx);
        sum += v[i];
    }
    #pragma unroll
    for (int o = 16; o > 0; o >>= 1)
        sum += __shfl_xor_sync(0xffffffffu, sum, o);
    if (lane == 0) red_sum[wid] = sum;
    __syncthreads();
    sum = 0.0f;
    #pragma unroll
    for (int w = 0; w < 8; w++) sum += red_sum[w];

    float inv = 1.0f / sum;
    uint2 o0, o1;
    o0.x = pack_bf16(v[0] * inv, v[1] * inv);
    o0.y = pack_bf16(v[2] * inv, v[3] * inv);
    o1.x = pack_bf16(v[4] * inv, v[5] * inv);
    o1.y = pack_bf16(v[6] * inv, v[7] * inv);
    reinterpret_cast<uint2*>(po)[tid] = o0;
    reinterpret_cast<uint2*>(po)[tid + 256] = o1;
}

// ---------------------------------------------------------------------------
extern "C" void kernel_launch(void* const* d_in, const int* in_sizes, int n_in,
                              void* d_out, int out_size)
{
    const float* classical = (const float*)d_in[0];
    const float* quantum   = (const float*)d_in[1];
    const float* Wc        = (const float*)d_in[2];
    const float* bc        = (const float*)d_in[3];
    const float* Wq        = (const float*)d_in[4];
    const float* bq        = (const float*)d_in[5];
    const float* Wg        = (const float*)d_in[6];
    const float* bg        = (const float*)d_in[7];
    const float* temp      = (const float*)d_in[8];
    float* out             = (float*)d_out;

    __nv_bfloat16 *cls_bf, *q_bf, *Wc_bf, *Wq_bf, *Wg_bf, *cproj, *qproj, *qT, *attn;
    float *iface, *sim;
    cudaGetSymbolAddress((void**)&cls_bf, g_cls_bf);
    cudaGetSymbolAddress((void**)&q_bf,   g_q_bf);
    cudaGetSymbolAddress((void**)&Wc_bf,  g_Wc_bf);
    cudaGetSymbolAddress((void**)&Wq_bf,  g_Wq_bf);
    cudaGetSymbolAddress((void**)&Wg_bf,  g_Wg_bf);
    cudaGetSymbolAddress((void**)&cproj,  g_cproj);
    cudaGetSymbolAddress((void**)&qproj,  g_qproj);
    cudaGetSymbolAddress((void**)&qT,     g_qT);
    cudaGetSymbolAddress((void**)&attn,   g_attn);
    cudaGetSymbolAddress((void**)&iface,  g_iface);
    cudaGetSymbolAddress((void**)&sim,    g_sim);

    cudaFuncSetAttribute(gemm_bf_kernel,
                         cudaFuncAttributeMaxDynamicSharedMemorySize, SM_TOTAL);

    dim3 blk(256);

    // Convert all inputs to bf16 (single launch, 1 float4/thread)
    tobf16_all_kernel<<<(unsigned)(N4_TOTAL/256), 256>>>(
        classical, quantum, Wc, Wq, Wg,
        cls_bf, q_bf, Wc_bf, Wq_bf, Wg_bf);

    // 0) qT[b] = bf16(quantum[b]^T)  [D,S]
    transpose_kernel<<<dim3(DD/32, SS/32, BB), 256>>>(quantum, qT);

    // 1+2) fused dual projection:
    //   z=0: cproj = bf16(classical @ Wc^T + bc)
    //   z=1: qproj = bf16(quantum   @ Wq^T + bq)
    gemm_bf_kernel<<<dim3(DD/128, MS/128, 2), blk, SM_TOTAL>>>(
        cls_bf, nullptr, Wc_bf, bc, nullptr, nullptr, cproj,
        q_bf, Wq_bf, bq, qproj,
        DD, DD, DD, DD, 0, 0, 0, 0);

    // 3) iface = sigmoid([cproj|qproj] @ Wg^T + bg), K=2048 split at 1024
    gemm_bf_kernel<<<dim3(DD/128, MS/128, 1), blk, SM_TOTAL>>>(
        cproj, qproj, Wg_bf, bg, nullptr, nullptr, iface,
        nullptr, nullptr, nullptr, nullptr,
        DD, 2*DD, DD, DD, 0, 0, 0, 1);

    // 4) sim[b] = cproj[b] @ qproj[b]^T  (raw fp32; scale folded into softmax)
    gemm_bf_kernel<<<dim3(SS/128, SS/128, BB), blk, SM_TOTAL>>>(
        cproj, nullptr, qproj, nullptr, nullptr, nullptr, sim,
        nullptr, nullptr, nullptr, nullptr,
        SS, DD, DD, DD,
        (long)SS*DD, (long)SS*DD, (long)SS*SS, 2);

    // 5) softmax -> bf16 attn
    softmax_kernel<<<BB*SS, 256>>>(sim, attn, temp);

    // 6) out = classical + iface * (attn[b] @ qT[b]^T)
    gemm_bf_kernel<<<dim3(DD/128, SS/128, BB), blk, SM_TOTAL>>>(
        attn, nullptr, qT, nullptr, classical, iface, out,
        nullptr, nullptr, nullptr, nullptr,
        DD, SS, SS, SS,
        (long)SS*SS, (long)DD*SS, (long)SS*DD, 3);
}